// round 1
// baseline (speedup 1.0000x reference)
#include <cuda_runtime.h>
#include <math.h>

#define NB     8
#define NPT    8192
#define SPT    2048
#define C_IN   256
#define C_SKIP 128
#define C_NP   384
#define C_OUT  256
#define C_E    1024
#define NGRP   8

// ---------------- scratch (device globals; no allocation allowed) -----------
static __device__ float g_np[(size_t)NB * C_NP * NPT];   // new_points  [B,384,N]
static __device__ float g_x [(size_t)NB * C_OUT * NPT];  // x / identity [B,256,N]
static __device__ float g_h1[(size_t)NB * C_E * NPT];    // hidden      [B,1024,N]
static __device__ float g_h2[(size_t)NB * C_OUT * NPT];  // c2 out raw  [B,256,N]
static __device__ float g_w3[(size_t)NB * NPT * 3];
static __device__ int   g_i3[(size_t)NB * NPT * 3];
static __device__ float g_stats[NB * NGRP * 2];          // mean, rstd per (b,g)
static __device__ float g_scale[NB * C_OUT];
static __device__ float g_shift[NB * C_OUT];

// ---------------- 3-NN + interpolation weights ------------------------------
__global__ void knn3_kernel(const float* __restrict__ xyz1,
                            const float* __restrict__ xyz2) {
    __shared__ float sx[SPT], sy[SPT], sz[SPT], sq[SPT];
    const int b = blockIdx.y;
    const float* x2 = xyz2 + (size_t)b * 3 * SPT;
    for (int s = threadIdx.x; s < SPT; s += blockDim.x) {
        float qx = x2[s], qy = x2[SPT + s], qz = x2[2 * SPT + s];
        sx[s] = qx; sy[s] = qy; sz[s] = qz;
        sq[s] = qx * qx + qy * qy + qz * qz;
    }
    __syncthreads();

    const int n = blockIdx.x * blockDim.x + threadIdx.x;
    const float* x1 = xyz1 + (size_t)b * 3 * NPT;
    const float px = x1[n], py = x1[NPT + n], pz = x1[2 * NPT + n];
    const float pn = px * px + py * py + pz * pz;

    float d0 = 3.4e38f, d1 = 3.4e38f, d2 = 3.4e38f;
    int   i0 = 0, i1 = 0, i2 = 0;
    for (int s = 0; s < SPT; s++) {
        // same formula as reference: -2*dot + |p|^2 + |q|^2
        float d = -2.f * (px * sx[s] + py * sy[s] + pz * sz[s]) + pn + sq[s];
        if (d < d0)      { d2 = d1; i2 = i1; d1 = d0; i1 = i0; d0 = d; i0 = s; }
        else if (d < d1) { d2 = d1; i2 = i1; d1 = d;  i1 = s; }
        else if (d < d2) { d2 = d;  i2 = s; }
    }
    float r0 = 1.f / (d0 + 1e-8f);
    float r1 = 1.f / (d1 + 1e-8f);
    float r2 = 1.f / (d2 + 1e-8f);
    float inv = 1.f / (r0 + r1 + r2);
    size_t o = ((size_t)b * NPT + n) * 3;
    g_w3[o + 0] = r0 * inv; g_w3[o + 1] = r1 * inv; g_w3[o + 2] = r2 * inv;
    g_i3[o + 0] = i0;       g_i3[o + 1] = i1;       g_i3[o + 2] = i2;
}

// ---------------- build new_points = concat(points1, interp) ----------------
__global__ void build_np_kernel(const float* __restrict__ points1,
                                const float* __restrict__ points2) {
    const int bc = blockIdx.x;
    const int b = bc / C_NP;
    const int c = bc % C_NP;
    float* dst = g_np + ((size_t)b * C_NP + c) * NPT;
    if (c < C_SKIP) {
        const float* src = points1 + ((size_t)b * C_SKIP + c) * NPT;
        for (int n = threadIdx.x; n < NPT; n += blockDim.x) dst[n] = src[n];
    } else {
        __shared__ float row[SPT];
        const float* src = points2 + ((size_t)b * C_IN + (c - C_SKIP)) * SPT;
        for (int s = threadIdx.x; s < SPT; s += blockDim.x) row[s] = src[s];
        __syncthreads();
        for (int n = threadIdx.x; n < NPT; n += blockDim.x) {
            size_t o = ((size_t)b * NPT + n) * 3;
            float v = g_w3[o + 0] * row[g_i3[o + 0]]
                    + g_w3[o + 1] * row[g_i3[o + 1]]
                    + g_w3[o + 2] * row[g_i3[o + 2]];
            dst[n] = v;
        }
    }
}

// ---------------- batched SGEMM: Y[b] = W(MxK) @ X[b](K x NPT) + bias -------
// grid: (NPT/64, M/64, NB)   block: 256
__global__ void gemm_bias_kernel(const float* __restrict__ W,
                                 const float* __restrict__ X,
                                 const float* __restrict__ bias,
                                 float* __restrict__ Y,
                                 int M, int K) {
    const int BM = 64, BN = 64, BK = 16;
    __shared__ float Ws[BK][BM];
    __shared__ float Xs[BK][BN];

    const float* Xb = X + (size_t)blockIdx.z * K * NPT;
    float*       Yb = Y + (size_t)blockIdx.z * M * NPT;
    const int m0 = blockIdx.y * BM;
    const int n0 = blockIdx.x * BN;
    const int tid = threadIdx.x;
    const int ty = tid / 16;   // 0..15 -> m sub-tile
    const int tx = tid % 16;   // 0..15 -> n sub-tile

    float acc[4][4] = {};

    for (int k0 = 0; k0 < K; k0 += BK) {
        // load W tile (BM x BK) as float4 along k, store transposed
        {
            int mr = tid / 4;
            int kc = (tid % 4) * 4;
            float4 wv = *reinterpret_cast<const float4*>(
                &W[(size_t)(m0 + mr) * K + k0 + kc]);
            Ws[kc + 0][mr] = wv.x;
            Ws[kc + 1][mr] = wv.y;
            Ws[kc + 2][mr] = wv.z;
            Ws[kc + 3][mr] = wv.w;
        }
        // load X tile (BK x BN) as float4 along n
        {
            int e  = tid * 4;
            int kr = e / BN;
            int nc = e % BN;
            float4 xv = *reinterpret_cast<const float4*>(
                &Xb[(size_t)(k0 + kr) * NPT + n0 + nc]);
            *reinterpret_cast<float4*>(&Xs[kr][nc]) = xv;
        }
        __syncthreads();

#pragma unroll
        for (int kk = 0; kk < BK; kk++) {
            float a[4], bv[4];
#pragma unroll
            for (int i = 0; i < 4; i++) a[i]  = Ws[kk][ty * 4 + i];
#pragma unroll
            for (int j = 0; j < 4; j++) bv[j] = Xs[kk][tx * 4 + j];
#pragma unroll
            for (int i = 0; i < 4; i++)
#pragma unroll
                for (int j = 0; j < 4; j++)
                    acc[i][j] += a[i] * bv[j];
        }
        __syncthreads();
    }

#pragma unroll
    for (int i = 0; i < 4; i++) {
        float bm = bias[m0 + ty * 4 + i];
        float4 v;
        v.x = acc[i][0] + bm; v.y = acc[i][1] + bm;
        v.z = acc[i][2] + bm; v.w = acc[i][3] + bm;
        *reinterpret_cast<float4*>(
            &Yb[(size_t)(m0 + ty * 4 + i) * NPT + n0 + tx * 4]) = v;
    }
}

// ---------------- group-norm statistics (groups are contiguous spans) -------
__global__ void gn_stats_kernel(const float* __restrict__ src, int C,
                                float* __restrict__ stats) {
    __shared__ float rs[256], rq[256];
    const int bg = blockIdx.x;          // b*NGRP + g
    const int Cg = C / NGRP;
    const size_t base = (size_t)bg * Cg * NPT;   // contiguous span
    const size_t cnt  = (size_t)Cg * NPT;
    float s = 0.f, q = 0.f;
    for (size_t i = threadIdx.x; i < cnt; i += 256) {
        float v = src[base + i];
        s += v; q += v * v;
    }
    rs[threadIdx.x] = s; rq[threadIdx.x] = q;
    __syncthreads();
    for (int o = 128; o > 0; o >>= 1) {
        if (threadIdx.x < o) {
            rs[threadIdx.x] += rs[threadIdx.x + o];
            rq[threadIdx.x] += rq[threadIdx.x + o];
        }
        __syncthreads();
    }
    if (threadIdx.x == 0) {
        float m   = rs[0] / (float)cnt;
        float var = rq[0] / (float)cnt - m * m;
        stats[bg * 2 + 0] = m;
        stats[bg * 2 + 1] = rsqrtf(var + 1e-5f);
    }
}

// ---------------- in-place GN apply (+ optional SiLU) -----------------------
__global__ void gn_apply_kernel(float* __restrict__ x,
                                const float* __restrict__ gw,
                                const float* __restrict__ gb,
                                const float* __restrict__ stats,
                                int C, int do_silu) {
    const size_t i = (size_t)blockIdx.x * 256 + threadIdx.x;
    const int Cg = C / NGRP;
    const int c  = (int)((i / NPT) % C);
    const int bg = (int)(i / ((size_t)Cg * NPT));
    const float m = stats[bg * 2 + 0];
    const float r = stats[bg * 2 + 1];
    float v = (x[i] - m) * r * gw[c] + gb[c];
    if (do_silu) v = v * (1.f / (1.f + expf(-v)));
    x[i] = v;
}

// ---------------- FiLM scale/shift from t_emb, c_emb ------------------------
__global__ void scaleshift_kernel(const float* __restrict__ t_emb,
                                  const float* __restrict__ c_emb,
                                  const float* __restrict__ tw,
                                  const float* __restrict__ tb,
                                  const float* __restrict__ cw,
                                  const float* __restrict__ cb) {
    __shared__ float te[C_OUT], ce[C_OUT];
    const int b = blockIdx.x;
    const int c = threadIdx.x;      // 256 threads
    te[c] = t_emb[b * C_OUT + c];
    ce[c] = c_emb[b * C_OUT + c];
    __syncthreads();
    float sc = tb[c] + cb[c];
    float sh = tb[c + C_OUT] + cb[c + C_OUT];
    const float* twr_s = tw + (size_t)c * C_OUT;
    const float* twr_h = tw + (size_t)(c + C_OUT) * C_OUT;
    const float* cwr_s = cw + (size_t)c * C_OUT;
    const float* cwr_h = cw + (size_t)(c + C_OUT) * C_OUT;
    for (int k = 0; k < C_OUT; k++) {
        sc += te[k] * twr_s[k] + ce[k] * cwr_s[k];
        sh += te[k] * twr_h[k] + ce[k] * cwr_h[k];
    }
    g_scale[b * C_OUT + c] = sc;
    g_shift[b * C_OUT + c] = sh;
}

// ---------------- final: GN(h2) * (1+scale) + shift + identity --------------
__global__ void final_kernel(const float* __restrict__ g2w,
                             const float* __restrict__ g2b,
                             float* __restrict__ out) {
    const size_t i = (size_t)blockIdx.x * 256 + threadIdx.x;
    const int Cg = C_OUT / NGRP;
    const int c  = (int)((i / NPT) % C_OUT);
    const int bg = (int)(i / ((size_t)Cg * NPT));
    const int bc = (int)(i / NPT);    // b*C_OUT + c
    const float m = g_stats[bg * 2 + 0];
    const float r = g_stats[bg * 2 + 1];
    float h = (g_h2[i] - m) * r * g2w[c] + g2b[c];
    out[i] = h * (1.f + g_scale[bc]) + g_shift[bc] + g_x[i];
}

// ---------------- launch ----------------------------------------------------
extern "C" void kernel_launch(void* const* d_in, const int* in_sizes, int n_in,
                              void* d_out, int out_size) {
    const float* xyz1    = (const float*)d_in[0];
    const float* points1 = (const float*)d_in[1];
    const float* xyz2    = (const float*)d_in[2];
    const float* points2 = (const float*)d_in[3];
    const float* t_emb   = (const float*)d_in[4];
    const float* c_emb   = (const float*)d_in[5];
    const float* mlp_w   = (const float*)d_in[6];
    const float* mlp_b   = (const float*)d_in[7];
    const float* mlp_gw  = (const float*)d_in[8];
    const float* mlp_gb  = (const float*)d_in[9];
    const float* c1w     = (const float*)d_in[10];
    const float* c1b     = (const float*)d_in[11];
    const float* g1w     = (const float*)d_in[12];
    const float* g1b     = (const float*)d_in[13];
    const float* c2w     = (const float*)d_in[14];
    const float* c2b     = (const float*)d_in[15];
    const float* g2w     = (const float*)d_in[16];
    const float* g2b     = (const float*)d_in[17];
    const float* tw      = (const float*)d_in[18];
    const float* tb      = (const float*)d_in[19];
    const float* cw      = (const float*)d_in[20];
    const float* cb      = (const float*)d_in[21];
    float* out = (float*)d_out;

    float *p_np, *p_x, *p_h1, *p_h2, *p_stats;
    cudaGetSymbolAddress((void**)&p_np, g_np);
    cudaGetSymbolAddress((void**)&p_x, g_x);
    cudaGetSymbolAddress((void**)&p_h1, g_h1);
    cudaGetSymbolAddress((void**)&p_h2, g_h2);
    cudaGetSymbolAddress((void**)&p_stats, g_stats);

    // 1) 3-NN + weights
    knn3_kernel<<<dim3(NPT / 256, NB), 256>>>(xyz1, xyz2);
    // 2) new_points = concat(points1, interp)
    build_np_kernel<<<NB * C_NP, 256>>>(points1, points2);
    // 3) FiLM scale/shift (independent, tiny)
    scaleshift_kernel<<<NB, 256>>>(t_emb, c_emb, tw, tb, cw, cb);

    // 4) x = silu(gn(mlp_w @ new_points + mlp_b))
    gemm_bias_kernel<<<dim3(NPT / 64, C_OUT / 64, NB), 256>>>(
        mlp_w, p_np, mlp_b, p_x, C_OUT, C_NP);
    gn_stats_kernel<<<NB * NGRP, 256>>>(p_x, C_OUT, p_stats);
    gn_apply_kernel<<<(int)(((size_t)NB * C_OUT * NPT) / 256), 256>>>(
        p_x, mlp_gw, mlp_gb, p_stats, C_OUT, 1);

    // 5) h = silu(gn(c1w @ x + c1b))
    gemm_bias_kernel<<<dim3(NPT / 64, C_E / 64, NB), 256>>>(
        c1w, p_x, c1b, p_h1, C_E, C_OUT);
    gn_stats_kernel<<<NB * NGRP, 256>>>(p_h1, C_E, p_stats);
    gn_apply_kernel<<<(int)(((size_t)NB * C_E * NPT) / 256), 256>>>(
        p_h1, g1w, g1b, p_stats, C_E, 1);

    // 6) h2 = c2w @ h + c2b ; gn stats
    gemm_bias_kernel<<<dim3(NPT / 64, C_OUT / 64, NB), 256>>>(
        c2w, p_h1, c2b, p_h2, C_OUT, C_E);
    gn_stats_kernel<<<NB * NGRP, 256>>>(p_h2, C_OUT, p_stats);

    // 7) out = gn(h2)*(1+scale) + shift + identity
    final_kernel<<<(int)(((size_t)NB * C_OUT * NPT) / 256), 256>>>(
        g2w, g2b, out);
}

// round 7
// speedup vs baseline: 2.1862x; 2.1862x over previous
#include <cuda_runtime.h>
#include <cuda_bf16.h>
#include <cstdint>
#include <math.h>

#define NB     8
#define NPT    8192
#define SPT    2048
#define C_IN   256
#define C_SKIP 128
#define C_NP   384
#define C_OUT  256
#define C_E    1024
#define NGRP   8

// ---------------- scratch (device globals; no allocation allowed) -----------
static __device__ float g_np[(size_t)NB * C_NP * NPT];
static __device__ float g_x [(size_t)NB * C_OUT * NPT];
static __device__ float g_h1[(size_t)NB * C_E * NPT];
static __device__ float g_h2[(size_t)NB * C_OUT * NPT];
static __device__ float g_w3[(size_t)NB * NPT * 3];
static __device__ int   g_i3[(size_t)NB * NPT * 3];
static __device__ float g_part[NB * NGRP * 32 * 2];
static __device__ float g_stats[NB * NGRP * 2];
static __device__ float g_scale[NB * C_OUT];
static __device__ float g_shift[NB * C_OUT];

// transposed bf16 split operands: Xt[b][n][k], k contiguous
static __device__ __nv_bfloat16 g_XtNpHi[(size_t)NB * NPT * C_NP];
static __device__ __nv_bfloat16 g_XtNpLo[(size_t)NB * NPT * C_NP];
static __device__ __nv_bfloat16 g_XtXHi [(size_t)NB * NPT * C_OUT];
static __device__ __nv_bfloat16 g_XtXLo [(size_t)NB * NPT * C_OUT];
static __device__ __nv_bfloat16 g_XtH1Hi[(size_t)NB * NPT * C_E];
static __device__ __nv_bfloat16 g_XtH1Lo[(size_t)NB * NPT * C_E];

// weight splits, [M,K] K-contiguous
static __device__ __nv_bfloat16 g_WnpHi[C_OUT * C_NP], g_WnpLo[C_OUT * C_NP];
static __device__ __nv_bfloat16 g_W1Hi [C_E * C_OUT],  g_W1Lo [C_E * C_OUT];
static __device__ __nv_bfloat16 g_W2Hi [C_OUT * C_E],  g_W2Lo [C_OUT * C_E];

__device__ __forceinline__ uint32_t smem_u32(const void* p) {
    uint32_t a;
    asm("{ .reg .u64 t; cvta.to.shared.u64 t, %1; cvt.u32.u64 %0, t; }"
        : "=r"(a) : "l"(p));
    return a;
}

// ======================= 3-NN + weights =====================================
__global__ void knn3_kernel(const float* __restrict__ xyz1,
                            const float* __restrict__ xyz2) {
    __shared__ float sx[SPT], sy[SPT], sz[SPT], sq[SPT];
    const int b = blockIdx.y;
    const float* x2 = xyz2 + (size_t)b * 3 * SPT;
    for (int s = threadIdx.x; s < SPT; s += blockDim.x) {
        float qx = x2[s], qy = x2[SPT + s], qz = x2[2 * SPT + s];
        sx[s] = qx; sy[s] = qy; sz[s] = qz;
        sq[s] = qx * qx + qy * qy + qz * qz;
    }
    __syncthreads();
    const int n = blockIdx.x * blockDim.x + threadIdx.x;
    const float* x1 = xyz1 + (size_t)b * 3 * NPT;
    const float px = x1[n], py = x1[NPT + n], pz = x1[2 * NPT + n];
    const float pn = px * px + py * py + pz * pz;
    float d0 = 3.4e38f, d1 = 3.4e38f, d2 = 3.4e38f;
    int   i0 = 0, i1 = 0, i2 = 0;
    for (int s = 0; s < SPT; s++) {
        float d = -2.f * (px * sx[s] + py * sy[s] + pz * sz[s]) + pn + sq[s];
        if (d < d0)      { d2 = d1; i2 = i1; d1 = d0; i1 = i0; d0 = d; i0 = s; }
        else if (d < d1) { d2 = d1; i2 = i1; d1 = d;  i1 = s; }
        else if (d < d2) { d2 = d;  i2 = s; }
    }
    float r0 = 1.f / (d0 + 1e-8f);
    float r1 = 1.f / (d1 + 1e-8f);
    float r2 = 1.f / (d2 + 1e-8f);
    float inv = 1.f / (r0 + r1 + r2);
    size_t o = ((size_t)b * NPT + n) * 3;
    g_w3[o + 0] = r0 * inv; g_w3[o + 1] = r1 * inv; g_w3[o + 2] = r2 * inv;
    g_i3[o + 0] = i0;       g_i3[o + 1] = i1;       g_i3[o + 2] = i2;
}

// ---------------- build new_points fp32 -------------------------------------
__global__ void build_np_kernel(const float* __restrict__ points1,
                                const float* __restrict__ points2) {
    const int bc = blockIdx.x;
    const int b = bc / C_NP;
    const int c = bc % C_NP;
    float* dst = g_np + ((size_t)b * C_NP + c) * NPT;
    if (c < C_SKIP) {
        const float* src = points1 + ((size_t)b * C_SKIP + c) * NPT;
        for (int n = threadIdx.x; n < NPT; n += blockDim.x) dst[n] = src[n];
    } else {
        __shared__ float row[SPT];
        const float* src = points2 + ((size_t)b * C_IN + (c - C_SKIP)) * SPT;
        for (int s = threadIdx.x; s < SPT; s += blockDim.x) row[s] = src[s];
        __syncthreads();
        for (int n = threadIdx.x; n < NPT; n += blockDim.x) {
            size_t o = ((size_t)b * NPT + n) * 3;
            dst[n] = g_w3[o + 0] * row[g_i3[o + 0]]
                   + g_w3[o + 1] * row[g_i3[o + 1]]
                   + g_w3[o + 2] * row[g_i3[o + 2]];
        }
    }
}

// ---------------- weight split to bf16 hi/lo --------------------------------
__global__ void wsplit_kernel(const float* __restrict__ w,
                              __nv_bfloat16* __restrict__ hi,
                              __nv_bfloat16* __restrict__ lo, int n) {
    int i = blockIdx.x * 256 + threadIdx.x;
    if (i < n) {
        float v = w[i];
        __nv_bfloat16 h = __float2bfloat16(v);
        hi[i] = h;
        lo[i] = __float2bfloat16(v - __bfloat162float(h));
    }
}

// ---------------- fused (GN+SiLU)? + transpose + bf16 split -----------------
__global__ void tsplit_kernel(const float* __restrict__ src,
                              __nv_bfloat16* __restrict__ hiD,
                              __nv_bfloat16* __restrict__ loD,
                              float* __restrict__ wb,
                              const float* __restrict__ gw,
                              const float* __restrict__ gb,
                              const float* __restrict__ stats,
                              int C, int mode) {
    __shared__ float s[32][33];
    const int b = blockIdx.z;
    const int n = blockIdx.x * 32 + threadIdx.x;
    const int Cg = C / NGRP;
#pragma unroll
    for (int i = 0; i < 4; i++) {
        int c = blockIdx.y * 32 + threadIdx.y + i * 8;
        size_t idx = ((size_t)b * C + c) * NPT + n;
        float v = src[idx];
        if (mode) {
            int bg = b * NGRP + c / Cg;
            float m = stats[bg * 2 + 0];
            float r = stats[bg * 2 + 1];
            v = (v - m) * r * gw[c] + gb[c];
            v = v * (1.f / (1.f + expf(-v)));          // SiLU
            if (wb) wb[idx] = v;
        }
        s[threadIdx.y + i * 8][threadIdx.x] = v;
    }
    __syncthreads();
    const int cg = blockIdx.y * 32 + threadIdx.x;
#pragma unroll
    for (int i = 0; i < 4; i++) {
        int n2 = blockIdx.x * 32 + threadIdx.y + i * 8;
        float v = s[threadIdx.x][threadIdx.y + i * 8];
        __nv_bfloat16 h = __float2bfloat16(v);
        size_t o = ((size_t)b * NPT + n2) * C + cg;
        hiD[o] = h;
        loD[o] = __float2bfloat16(v - __bfloat162float(h));
    }
}

// ---------------- GN stats, 2-stage deterministic ---------------------------
__global__ void gn_part_kernel(const float* __restrict__ src, int C) {
    __shared__ float rs[256], rq[256];
    const int blk = blockIdx.x;
    const int slice = blk & 31;
    const int bg = blk >> 5;
    const size_t cnt = (size_t)(C / NGRP) * NPT;
    const size_t span = cnt / 32;
    const float* p = src + (size_t)bg * cnt + (size_t)slice * span;
    float sm = 0.f, sq = 0.f;
    for (size_t i = threadIdx.x * 4; i < span; i += 1024) {
        float4 v = *reinterpret_cast<const float4*>(p + i);
        sm += v.x + v.y + v.z + v.w;
        sq += v.x * v.x + v.y * v.y + v.z * v.z + v.w * v.w;
    }
    rs[threadIdx.x] = sm; rq[threadIdx.x] = sq;
    __syncthreads();
    for (int o = 128; o > 0; o >>= 1) {
        if (threadIdx.x < o) {
            rs[threadIdx.x] += rs[threadIdx.x + o];
            rq[threadIdx.x] += rq[threadIdx.x + o];
        }
        __syncthreads();
    }
    if (threadIdx.x == 0) {
        g_part[blk * 2 + 0] = rs[0];
        g_part[blk * 2 + 1] = rq[0];
    }
}
__global__ void gn_fin_kernel(int C) {
    int bg = threadIdx.x;
    if (bg < NB * NGRP) {
        float sm = 0.f, sq = 0.f;
        for (int s = 0; s < 32; s++) {
            sm += g_part[(bg * 32 + s) * 2 + 0];
            sq += g_part[(bg * 32 + s) * 2 + 1];
        }
        float cnt = (float)((size_t)(C / NGRP) * NPT);
        float m = sm / cnt;
        float var = sq / cnt - m * m;
        g_stats[bg * 2 + 0] = m;
        g_stats[bg * 2 + 1] = rsqrtf(var + 1e-5f);
    }
}

// ======================= mma.sync split-bf16 GEMM ===========================
// Y[b](M x 8192) = W(MxK) @ X[b](K x 8192) + bias.  A=W [M,K], B=Xt [N,K].
// CTA tile 128x128x32, 256 threads (8 warps, 2x4), warp tile 64x32.
// smem: double-buffered padded tiles, stride 40 bf16 (80B) per row.
#define TSTRIDE 40
#define TILE_E  (128 * TSTRIDE)          // 5120 bf16 per tile buffer
#define GEMM_SMEM_BYTES (8 * TILE_E * 2) // 4 arrays x 2 stages x 5120 x 2B = 81920

__device__ __forceinline__ void cp16(uint32_t saddr, const void* gaddr) {
    asm volatile("cp.async.cg.shared.global [%0], [%1], 16;"
                 :: "r"(saddr), "l"(gaddr));
}
__device__ __forceinline__ void ldsm_x4(uint32_t* r, uint32_t addr) {
    asm volatile("ldmatrix.sync.aligned.m8n8.x4.shared.b16 {%0,%1,%2,%3}, [%4];"
                 : "=r"(r[0]), "=r"(r[1]), "=r"(r[2]), "=r"(r[3]) : "r"(addr));
}
#define MMA_BF16(ac, a, b0, b1)                                               \
    asm volatile("mma.sync.aligned.m16n8k16.row.col.f32.bf16.bf16.f32 "       \
                 "{%0,%1,%2,%3}, {%4,%5,%6,%7}, {%8,%9}, {%0,%1,%2,%3};"      \
                 : "+f"((ac)[0]), "+f"((ac)[1]), "+f"((ac)[2]), "+f"((ac)[3]) \
                 : "r"((a)[0]), "r"((a)[1]), "r"((a)[2]), "r"((a)[3]),        \
                   "r"(b0), "r"(b1))

__global__ void __launch_bounds__(256, 1)
gemm_mma_kernel(const __nv_bfloat16* __restrict__ Whi,
                const __nv_bfloat16* __restrict__ Wlo,
                const __nv_bfloat16* __restrict__ Xhi,
                const __nv_bfloat16* __restrict__ Xlo,
                const float* __restrict__ bias,
                float* __restrict__ Y,
                int M, int K) {
    extern __shared__ __nv_bfloat16 smem[];
    const uint32_t sb = smem_u32(smem);
    const int tid  = threadIdx.x;
    const int wid  = tid >> 5;
    const int lane = tid & 31;

    const int n0 = blockIdx.x * 128;
    const int m0 = blockIdx.y * 128;
    const int b  = blockIdx.z;
    const __nv_bfloat16* XhiB = Xhi + (size_t)b * NPT * K;
    const __nv_bfloat16* XloB = Xlo + (size_t)b * NPT * K;
    float* Yb = Y + (size_t)b * M * NPT;

    const int wm = (wid >> 2) * 64;    // warp row base (M)
    const int wn = (wid & 3) * 32;     // warp col base (N)

    float acc[4][4][4];
#pragma unroll
    for (int i = 0; i < 4; i++)
#pragma unroll
        for (int j = 0; j < 4; j++)
#pragma unroll
            for (int q = 0; q < 4; q++) acc[i][j][q] = 0.f;

    const int row0 = tid >> 2,         seg0 = tid & 3;
    const int row1 = (tid + 256) >> 2, seg1 = (tid + 256) & 3;

    const int niter = K >> 5;   // BK=32

    auto load_stage = [&](int s, int k0) {
        const uint32_t aHiS = sb + (uint32_t)(0 * TILE_E + s * TILE_E) * 2;
        const uint32_t aLoS = sb + (uint32_t)(2 * TILE_E + s * TILE_E) * 2;
        const uint32_t bHiS = sb + (uint32_t)(4 * TILE_E + s * TILE_E) * 2;
        const uint32_t bLoS = sb + (uint32_t)(6 * TILE_E + s * TILE_E) * 2;
        {
            uint32_t so = (uint32_t)(row0 * TSTRIDE + seg0 * 8) * 2;
            size_t ga = (size_t)(m0 + row0) * K + k0 + seg0 * 8;
            size_t gb = (size_t)(n0 + row0) * K + k0 + seg0 * 8;
            cp16(aHiS + so, Whi + ga);
            cp16(aLoS + so, Wlo + ga);
            cp16(bHiS + so, XhiB + gb);
            cp16(bLoS + so, XloB + gb);
        }
        {
            uint32_t so = (uint32_t)(row1 * TSTRIDE + seg1 * 8) * 2;
            size_t ga = (size_t)(m0 + row1) * K + k0 + seg1 * 8;
            size_t gb = (size_t)(n0 + row1) * K + k0 + seg1 * 8;
            cp16(aHiS + so, Whi + ga);
            cp16(aLoS + so, Wlo + ga);
            cp16(bHiS + so, XhiB + gb);
            cp16(bLoS + so, XloB + gb);
        }
        asm volatile("cp.async.commit_group;" ::: "memory");
    };

    const int aRow = wm + (lane & 15);
    const int aKof = (lane >> 4) * 8;
    const int bRowP = ((lane >> 4) ? 8 : 0) + (lane & 7);
    const int bKof  = ((lane >> 3) & 1) * 8;

    load_stage(0, 0);

    for (int it = 0; it < niter; it++) {
        if (it + 1 < niter) {
            load_stage((it + 1) & 1, (it + 1) << 5);
            asm volatile("cp.async.wait_group 1;" ::: "memory");
        } else {
            asm volatile("cp.async.wait_group 0;" ::: "memory");
        }
        __syncthreads();

        const int s = it & 1;
        const uint32_t aHiS = sb + (uint32_t)(0 * TILE_E + s * TILE_E) * 2;
        const uint32_t aLoS = sb + (uint32_t)(2 * TILE_E + s * TILE_E) * 2;
        const uint32_t bHiS = sb + (uint32_t)(4 * TILE_E + s * TILE_E) * 2;
        const uint32_t bLoS = sb + (uint32_t)(6 * TILE_E + s * TILE_E) * 2;

#pragma unroll
        for (int kk = 0; kk < 2; kk++) {
            uint32_t ahi[4][4], alo[4][4], bhi[4][2], blo[4][2];
#pragma unroll
            for (int mf = 0; mf < 4; mf++) {
                uint32_t off = (uint32_t)((aRow + mf * 16) * TSTRIDE
                                          + kk * 16 + aKof) * 2;
                ldsm_x4(ahi[mf], aHiS + off);
                ldsm_x4(alo[mf], aLoS + off);
            }
#pragma unroll
            for (int p = 0; p < 2; p++) {
                uint32_t off = (uint32_t)((wn + p * 16 + bRowP) * TSTRIDE
                                          + kk * 16 + bKof) * 2;
                uint32_t r[4];
                ldsm_x4(r, bHiS + off);
                bhi[2 * p][0] = r[0]; bhi[2 * p][1] = r[1];
                bhi[2 * p + 1][0] = r[2]; bhi[2 * p + 1][1] = r[3];
                ldsm_x4(r, bLoS + off);
                blo[2 * p][0] = r[0]; blo[2 * p][1] = r[1];
                blo[2 * p + 1][0] = r[2]; blo[2 * p + 1][1] = r[3];
            }
#pragma unroll
            for (int mf = 0; mf < 4; mf++)
#pragma unroll
                for (int nf = 0; nf < 4; nf++) {
                    MMA_BF16(acc[mf][nf], ahi[mf], bhi[nf][0], bhi[nf][1]);
                    MMA_BF16(acc[mf][nf], ahi[mf], blo[nf][0], blo[nf][1]);
                    MMA_BF16(acc[mf][nf], alo[mf], bhi[nf][0], bhi[nf][1]);
                }
        }
        __syncthreads();
    }

    const int gid  = lane >> 2;
    const int tid4 = lane & 3;
#pragma unroll
    for (int mf = 0; mf < 4; mf++) {
        const int m = m0 + wm + mf * 16 + gid;
        const float bm0 = bias[m];
        const float bm8 = bias[m + 8];
        float* y0 = Yb + (size_t)m * NPT;
        float* y8 = Yb + (size_t)(m + 8) * NPT;
#pragma unroll
        for (int nf = 0; nf < 4; nf++) {
            const int n = n0 + wn + nf * 8 + 2 * tid4;
            float2 v0 = make_float2(acc[mf][nf][0] + bm0, acc[mf][nf][1] + bm0);
            float2 v8 = make_float2(acc[mf][nf][2] + bm8, acc[mf][nf][3] + bm8);
            *reinterpret_cast<float2*>(y0 + n) = v0;
            *reinterpret_cast<float2*>(y8 + n) = v8;
        }
    }
}

// ---------------- FiLM scale/shift ------------------------------------------
__global__ void scaleshift_kernel(const float* __restrict__ t_emb,
                                  const float* __restrict__ c_emb,
                                  const float* __restrict__ tw,
                                  const float* __restrict__ tb,
                                  const float* __restrict__ cw,
                                  const float* __restrict__ cb) {
    __shared__ float te[C_OUT], ce[C_OUT];
    const int b = blockIdx.x;
    const int c = threadIdx.x;
    te[c] = t_emb[b * C_OUT + c];
    ce[c] = c_emb[b * C_OUT + c];
    __syncthreads();
    float sc = tb[c] + cb[c];
    float sh = tb[c + C_OUT] + cb[c + C_OUT];
    const float* twr_s = tw + (size_t)c * C_OUT;
    const float* twr_h = tw + (size_t)(c + C_OUT) * C_OUT;
    const float* cwr_s = cw + (size_t)c * C_OUT;
    const float* cwr_h = cw + (size_t)(c + C_OUT) * C_OUT;
    for (int k = 0; k < C_OUT; k++) {
        sc += te[k] * twr_s[k] + ce[k] * cwr_s[k];
        sh += te[k] * twr_h[k] + ce[k] * cwr_h[k];
    }
    g_scale[b * C_OUT + c] = sc;
    g_shift[b * C_OUT + c] = sh;
}

// ---------------- final: GN(h2)*(1+scale)+shift+identity --------------------
__global__ void final_kernel(const float* __restrict__ g2w,
                             const float* __restrict__ g2b,
                             float* __restrict__ out) {
    const size_t i = (size_t)blockIdx.x * 256 + threadIdx.x;
    const int Cg = C_OUT / NGRP;
    const int c  = (int)((i / NPT) % C_OUT);
    const int bg = (int)(i / ((size_t)Cg * NPT));
    const int bc = (int)(i / NPT);
    const float m = g_stats[bg * 2 + 0];
    const float r = g_stats[bg * 2 + 1];
    float h = (g_h2[i] - m) * r * g2w[c] + g2b[c];
    out[i] = h * (1.f + g_scale[bc]) + g_shift[bc] + g_x[i];
}

// ======================= launch =============================================
extern "C" void kernel_launch(void* const* d_in, const int* in_sizes, int n_in,
                              void* d_out, int out_size) {
    const float* xyz1    = (const float*)d_in[0];
    const float* points1 = (const float*)d_in[1];
    const float* xyz2    = (const float*)d_in[2];
    const float* points2 = (const float*)d_in[3];
    const float* t_emb   = (const float*)d_in[4];
    const float* c_emb   = (const float*)d_in[5];
    const float* mlp_w   = (const float*)d_in[6];
    const float* mlp_b   = (const float*)d_in[7];
    const float* mlp_gw  = (const float*)d_in[8];
    const float* mlp_gb  = (const float*)d_in[9];
    const float* c1w     = (const float*)d_in[10];
    const float* c1b     = (const float*)d_in[11];
    const float* g1w     = (const float*)d_in[12];
    const float* g1b     = (const float*)d_in[13];
    const float* c2w     = (const float*)d_in[14];
    const float* c2b     = (const float*)d_in[15];
    const float* g2w     = (const float*)d_in[16];
    const float* g2b     = (const float*)d_in[17];
    const float* tw      = (const float*)d_in[18];
    const float* tb      = (const float*)d_in[19];
    const float* cw      = (const float*)d_in[20];
    const float* cb      = (const float*)d_in[21];
    float* out = (float*)d_out;

    cudaFuncSetAttribute(gemm_mma_kernel,
                         cudaFuncAttributeMaxDynamicSharedMemorySize,
                         GEMM_SMEM_BYTES);

    float *p_np, *p_x, *p_h1, *p_h2, *p_stats;
    cudaGetSymbolAddress((void**)&p_np, g_np);
    cudaGetSymbolAddress((void**)&p_x, g_x);
    cudaGetSymbolAddress((void**)&p_h1, g_h1);
    cudaGetSymbolAddress((void**)&p_h2, g_h2);
    cudaGetSymbolAddress((void**)&p_stats, g_stats);
    __nv_bfloat16 *pWnpHi, *pWnpLo, *pW1Hi, *pW1Lo, *pW2Hi, *pW2Lo;
    __nv_bfloat16 *pXtNpHi, *pXtNpLo, *pXtXHi, *pXtXLo, *pXtH1Hi, *pXtH1Lo;
    cudaGetSymbolAddress((void**)&pWnpHi, g_WnpHi);
    cudaGetSymbolAddress((void**)&pWnpLo, g_WnpLo);
    cudaGetSymbolAddress((void**)&pW1Hi, g_W1Hi);
    cudaGetSymbolAddress((void**)&pW1Lo, g_W1Lo);
    cudaGetSymbolAddress((void**)&pW2Hi, g_W2Hi);
    cudaGetSymbolAddress((void**)&pW2Lo, g_W2Lo);
    cudaGetSymbolAddress((void**)&pXtNpHi, g_XtNpHi);
    cudaGetSymbolAddress((void**)&pXtNpLo, g_XtNpLo);
    cudaGetSymbolAddress((void**)&pXtXHi, g_XtXHi);
    cudaGetSymbolAddress((void**)&pXtXLo, g_XtXLo);
    cudaGetSymbolAddress((void**)&pXtH1Hi, g_XtH1Hi);
    cudaGetSymbolAddress((void**)&pXtH1Lo, g_XtH1Lo);

    // 1) independent prep
    knn3_kernel<<<dim3(NPT / 256, NB), 256>>>(xyz1, xyz2);
    build_np_kernel<<<NB * C_NP, 256>>>(points1, points2);
    scaleshift_kernel<<<NB, 256>>>(t_emb, c_emb, tw, tb, cw, cb);
    wsplit_kernel<<<(C_OUT * C_NP + 255) / 256, 256>>>(mlp_w, pWnpHi, pWnpLo, C_OUT * C_NP);
    wsplit_kernel<<<(C_E * C_OUT + 255) / 256, 256>>>(c1w, pW1Hi, pW1Lo, C_E * C_OUT);
    wsplit_kernel<<<(C_OUT * C_E + 255) / 256, 256>>>(c2w, pW2Hi, pW2Lo, C_OUT * C_E);

    // 2) np -> transposed bf16 split (no GN)
    tsplit_kernel<<<dim3(NPT / 32, C_NP / 32, NB), dim3(32, 8)>>>(
        p_np, pXtNpHi, pXtNpLo, nullptr, nullptr, nullptr, nullptr, C_NP, 0);

    // 3) GEMM1: x_raw = mlp_w @ np + mlp_b
    gemm_mma_kernel<<<dim3(NPT / 128, C_OUT / 128, NB), 256, GEMM_SMEM_BYTES>>>(
        pWnpHi, pWnpLo, pXtNpHi, pXtNpLo, mlp_b, p_x, C_OUT, C_NP);
    gn_part_kernel<<<NB * NGRP * 32, 256>>>(p_x, C_OUT);
    gn_fin_kernel<<<1, 128>>>(C_OUT);

    // 4) x = silu(gn(x_raw)); writeback + transposed split
    tsplit_kernel<<<dim3(NPT / 32, C_OUT / 32, NB), dim3(32, 8)>>>(
        p_x, pXtXHi, pXtXLo, p_x, mlp_gw, mlp_gb, p_stats, C_OUT, 1);

    // 5) GEMM2: h1_raw = c1w @ x + c1b
    gemm_mma_kernel<<<dim3(NPT / 128, C_E / 128, NB), 256, GEMM_SMEM_BYTES>>>(
        pW1Hi, pW1Lo, pXtXHi, pXtXLo, c1b, p_h1, C_E, C_OUT);
    gn_part_kernel<<<NB * NGRP * 32, 256>>>(p_h1, C_E);
    gn_fin_kernel<<<1, 128>>>(C_E);

    // 6) h = silu(gn(h1_raw)); transposed split
    tsplit_kernel<<<dim3(NPT / 32, C_E / 32, NB), dim3(32, 8)>>>(
        p_h1, pXtH1Hi, pXtH1Lo, nullptr, g1w, g1b, p_stats, C_E, 1);

    // 7) GEMM3: h2_raw = c2w @ h + c2b
    gemm_mma_kernel<<<dim3(NPT / 128, C_OUT / 128, NB), 256, GEMM_SMEM_BYTES>>>(
        pW2Hi, pW2Lo, pXtH1Hi, pXtH1Lo, c2b, p_h2, C_OUT, C_E);
    gn_part_kernel<<<NB * NGRP * 32, 256>>>(p_h2, C_OUT);
    gn_fin_kernel<<<1, 128>>>(C_OUT);

    // 8) out = gn(h2)*(1+scale) + shift + x
    final_kernel<<<(int)(((size_t)NB * C_OUT * NPT) / 256), 256>>>(g2w, g2b, out);
}

// round 9
// speedup vs baseline: 2.5631x; 1.1724x over previous
#include <cuda_runtime.h>
#include <cuda_fp16.h>
#include <cstdint>
#include <math.h>

#define NB     8
#define NPT    8192
#define SPT    2048
#define C_IN   256
#define C_SKIP 128
#define C_NP   384
#define C_OUT  256
#define C_E    1024
#define NGRP   8
#define NTILE  (NPT / 128)   // 64 n-tiles per GEMM

// ---------------- scratch (device globals; no allocation allowed) -----------
static __device__ float g_np[(size_t)NB * C_NP * NPT];
static __device__ float g_x [(size_t)NB * C_OUT * NPT];
static __device__ float g_h1[(size_t)NB * C_E * NPT];
static __device__ float g_h2[(size_t)NB * C_OUT * NPT];
static __device__ float g_w3[(size_t)NB * NPT * 3];
static __device__ int   g_i3[(size_t)NB * NPT * 3];
static __device__ float g_psum[NB * NGRP * NTILE];   // per-tile partial sums
static __device__ float g_psq [NB * NGRP * NTILE];
static __device__ float g_stats[NB * NGRP * 2];
static __device__ float g_scale[NB * C_OUT];
static __device__ float g_shift[NB * C_OUT];

// transposed fp16 operands: Xt[b][n][k], k contiguous (single, unsplit)
static __device__ __half g_XtNp[(size_t)NB * NPT * C_NP];
static __device__ __half g_XtX [(size_t)NB * NPT * C_OUT];
static __device__ __half g_XtH1[(size_t)NB * NPT * C_E];

// weight splits fp16 hi/lo, [M,K] K-contiguous
static __device__ __half g_WnpHi[C_OUT * C_NP], g_WnpLo[C_OUT * C_NP];
static __device__ __half g_W1Hi [C_E * C_OUT],  g_W1Lo [C_E * C_OUT];
static __device__ __half g_W2Hi [C_OUT * C_E],  g_W2Lo [C_OUT * C_E];

__device__ __forceinline__ uint32_t smem_u32(const void* p) {
    uint32_t a;
    asm("{ .reg .u64 t; cvta.to.shared.u64 t, %1; cvt.u32.u64 %0, t; }"
        : "=r"(a) : "l"(p));
    return a;
}

// ======================= 3-NN + weights =====================================
__global__ void knn3_kernel(const float* __restrict__ xyz1,
                            const float* __restrict__ xyz2) {
    __shared__ float sx[SPT], sy[SPT], sz[SPT], sq[SPT];
    const int b = blockIdx.y;
    const float* x2 = xyz2 + (size_t)b * 3 * SPT;
    for (int s = threadIdx.x; s < SPT; s += blockDim.x) {
        float qx = x2[s], qy = x2[SPT + s], qz = x2[2 * SPT + s];
        sx[s] = qx; sy[s] = qy; sz[s] = qz;
        sq[s] = qx * qx + qy * qy + qz * qz;
    }
    __syncthreads();
    const int n = blockIdx.x * blockDim.x + threadIdx.x;
    const float* x1 = xyz1 + (size_t)b * 3 * NPT;
    const float px = x1[n], py = x1[NPT + n], pz = x1[2 * NPT + n];
    const float pn = px * px + py * py + pz * pz;
    float d0 = 3.4e38f, d1 = 3.4e38f, d2 = 3.4e38f;
    int   i0 = 0, i1 = 0, i2 = 0;
    for (int s = 0; s < SPT; s++) {
        float d = -2.f * (px * sx[s] + py * sy[s] + pz * sz[s]) + pn + sq[s];
        if (d < d0)      { d2 = d1; i2 = i1; d1 = d0; i1 = i0; d0 = d; i0 = s; }
        else if (d < d1) { d2 = d1; i2 = i1; d1 = d;  i1 = s; }
        else if (d < d2) { d2 = d;  i2 = s; }
    }
    float r0 = 1.f / (d0 + 1e-8f);
    float r1 = 1.f / (d1 + 1e-8f);
    float r2 = 1.f / (d2 + 1e-8f);
    float inv = 1.f / (r0 + r1 + r2);
    size_t o = ((size_t)b * NPT + n) * 3;
    g_w3[o + 0] = r0 * inv; g_w3[o + 1] = r1 * inv; g_w3[o + 2] = r2 * inv;
    g_i3[o + 0] = i0;       g_i3[o + 1] = i1;       g_i3[o + 2] = i2;
}

// ---------------- build new_points fp32 -------------------------------------
__global__ void build_np_kernel(const float* __restrict__ points1,
                                const float* __restrict__ points2) {
    const int bc = blockIdx.x;
    const int b = bc / C_NP;
    const int c = bc % C_NP;
    float* dst = g_np + ((size_t)b * C_NP + c) * NPT;
    if (c < C_SKIP) {
        const float* src = points1 + ((size_t)b * C_SKIP + c) * NPT;
        for (int n = threadIdx.x; n < NPT; n += blockDim.x) dst[n] = src[n];
    } else {
        __shared__ float row[SPT];
        const float* src = points2 + ((size_t)b * C_IN + (c - C_SKIP)) * SPT;
        for (int s = threadIdx.x; s < SPT; s += blockDim.x) row[s] = src[s];
        __syncthreads();
        for (int n = threadIdx.x; n < NPT; n += blockDim.x) {
            size_t o = ((size_t)b * NPT + n) * 3;
            dst[n] = g_w3[o + 0] * row[g_i3[o + 0]]
                   + g_w3[o + 1] * row[g_i3[o + 1]]
                   + g_w3[o + 2] * row[g_i3[o + 2]];
        }
    }
}

// ---------------- weight split to fp16 hi/lo --------------------------------
__global__ void wsplit_kernel(const float* __restrict__ w,
                              __half* __restrict__ hi,
                              __half* __restrict__ lo, int n) {
    int i = blockIdx.x * 256 + threadIdx.x;
    if (i < n) {
        float v = w[i];
        __half h = __float2half(v);
        hi[i] = h;
        lo[i] = __float2half(v - __half2float(h));
    }
}

// ---------------- fused (GN+SiLU)? + transpose + fp16 convert ---------------
// src: [B,C,NPT] fp32.  dst: [B,NPT,C] fp16.  wb: optional fp32 writeback.
__global__ void tsplit_kernel(const float* __restrict__ src,
                              __half* __restrict__ dst,
                              float* __restrict__ wb,
                              const float* __restrict__ gw,
                              const float* __restrict__ gb,
                              const float* __restrict__ stats,
                              int C, int mode) {
    __shared__ float s[32][33];
    const int b = blockIdx.z;
    const int n = blockIdx.x * 32 + threadIdx.x;
    const int Cg = C / NGRP;
#pragma unroll
    for (int i = 0; i < 4; i++) {
        int c = blockIdx.y * 32 + threadIdx.y + i * 8;
        size_t idx = ((size_t)b * C + c) * NPT + n;
        float v = src[idx];
        if (mode) {
            int bg = b * NGRP + c / Cg;
            float m = stats[bg * 2 + 0];
            float r = stats[bg * 2 + 1];
            v = (v - m) * r * gw[c] + gb[c];
            v = v * (1.f / (1.f + expf(-v)));          // SiLU
            if (wb) wb[idx] = v;
        }
        s[threadIdx.y + i * 8][threadIdx.x] = v;
    }
    __syncthreads();
    const int cg = blockIdx.y * 32 + threadIdx.x;
#pragma unroll
    for (int i = 0; i < 4; i++) {
        int n2 = blockIdx.x * 32 + threadIdx.y + i * 8;
        float v = s[threadIdx.x][threadIdx.y + i * 8];
        dst[((size_t)b * NPT + n2) * C + cg] = __float2half(v);
    }
}

// ---------------- GN finalize: sum 64 per-tile partials ---------------------
__global__ void gn_fin_kernel(int C) {
    int bg = threadIdx.x;
    if (bg < NB * NGRP) {
        float sm = 0.f, sq = 0.f;
        for (int t = 0; t < NTILE; t++) {
            sm += g_psum[bg * NTILE + t];
            sq += g_psq [bg * NTILE + t];
        }
        float cnt = (float)((size_t)(C / NGRP) * NPT);
        float m = sm / cnt;
        float var = sq / cnt - m * m;
        g_stats[bg * 2 + 0] = m;
        g_stats[bg * 2 + 1] = rsqrtf(var + 1e-5f);
    }
}

// ======================= mma.sync fp16 split-W GEMM + fused stats ===========
// Y[b](M x 8192) = W(MxK) @ X[b](K x 8192) + bias.  A=W [M,K], B=Xt [N,K].
// CTA tile 128x128x32, 256 threads (8 warps, 2x4), warp tile 64x32.
// 2 MMAs per fragment: Whi*X + Wlo*X.  Epilogue also emits per-group
// partial sums/sumsq for GroupNorm into g_psum/g_psq (deterministic tree).
#define TSTRIDE 40
#define TILE_E  (128 * TSTRIDE)           // 5120 halfs per tile buffer
#define GEMM_SMEM_BYTES (6 * TILE_E * 2)  // 3 arrays x 2 stages = 61440 B

__device__ __forceinline__ void cp16(uint32_t saddr, const void* gaddr) {
    asm volatile("cp.async.cg.shared.global [%0], [%1], 16;"
                 :: "r"(saddr), "l"(gaddr));
}
__device__ __forceinline__ void ldsm_x4(uint32_t* r, uint32_t addr) {
    asm volatile("ldmatrix.sync.aligned.m8n8.x4.shared.b16 {%0,%1,%2,%3}, [%4];"
                 : "=r"(r[0]), "=r"(r[1]), "=r"(r[2]), "=r"(r[3]) : "r"(addr));
}
#define MMA_F16(ac, a, b0, b1)                                                \
    asm volatile("mma.sync.aligned.m16n8k16.row.col.f32.f16.f16.f32 "         \
                 "{%0,%1,%2,%3}, {%4,%5,%6,%7}, {%8,%9}, {%0,%1,%2,%3};"      \
                 : "+f"((ac)[0]), "+f"((ac)[1]), "+f"((ac)[2]), "+f"((ac)[3]) \
                 : "r"((a)[0]), "r"((a)[1]), "r"((a)[2]), "r"((a)[3]),        \
                   "r"(b0), "r"(b1))

__global__ void __launch_bounds__(256, 1)
gemm_mma_kernel(const __half* __restrict__ Whi,
                const __half* __restrict__ Wlo,
                const __half* __restrict__ X,
                const float* __restrict__ bias,
                float* __restrict__ Y,
                int M, int K) {
    extern __shared__ __half smem[];
    const uint32_t sb = smem_u32(smem);
    const int tid  = threadIdx.x;
    const int wid  = tid >> 5;
    const int lane = tid & 31;

    const int n0 = blockIdx.x * 128;
    const int m0 = blockIdx.y * 128;
    const int b  = blockIdx.z;
    const __half* XB = X + (size_t)b * NPT * K;
    float* Yb = Y + (size_t)b * M * NPT;

    const int wm = (wid >> 2) * 64;    // warp row base (M)
    const int wn = (wid & 3) * 32;     // warp col base (N)

    float acc[4][4][4];
#pragma unroll
    for (int i = 0; i < 4; i++)
#pragma unroll
        for (int j = 0; j < 4; j++)
#pragma unroll
            for (int q = 0; q < 4; q++) acc[i][j][q] = 0.f;

    const int row0 = tid >> 2,         seg0 = tid & 3;
    const int row1 = (tid + 256) >> 2, seg1 = (tid + 256) & 3;

    const int niter = K >> 5;   // BK=32

    auto load_stage = [&](int s, int k0) {
        const uint32_t aHiS = sb + (uint32_t)(0 * TILE_E + s * TILE_E) * 2;
        const uint32_t aLoS = sb + (uint32_t)(2 * TILE_E + s * TILE_E) * 2;
        const uint32_t bS   = sb + (uint32_t)(4 * TILE_E + s * TILE_E) * 2;
        {
            uint32_t so = (uint32_t)(row0 * TSTRIDE + seg0 * 8) * 2;
            size_t ga = (size_t)(m0 + row0) * K + k0 + seg0 * 8;
            size_t gb = (size_t)(n0 + row0) * K + k0 + seg0 * 8;
            cp16(aHiS + so, Whi + ga);
            cp16(aLoS + so, Wlo + ga);
            cp16(bS + so, XB + gb);
        }
        {
            uint32_t so = (uint32_t)(row1 * TSTRIDE + seg1 * 8) * 2;
            size_t ga = (size_t)(m0 + row1) * K + k0 + seg1 * 8;
            size_t gb = (size_t)(n0 + row1) * K + k0 + seg1 * 8;
            cp16(aHiS + so, Whi + ga);
            cp16(aLoS + so, Wlo + ga);
            cp16(bS + so, XB + gb);
        }
        asm volatile("cp.async.commit_group;" ::: "memory");
    };

    const int aRow = wm + (lane & 15);
    const int aKof = (lane >> 4) * 8;
    const int bRowP = ((lane >> 4) ? 8 : 0) + (lane & 7);
    const int bKof  = ((lane >> 3) & 1) * 8;

    load_stage(0, 0);

    for (int it = 0; it < niter; it++) {
        if (it + 1 < niter) {
            load_stage((it + 1) & 1, (it + 1) << 5);
            asm volatile("cp.async.wait_group 1;" ::: "memory");
        } else {
            asm volatile("cp.async.wait_group 0;" ::: "memory");
        }
        __syncthreads();

        const int s = it & 1;
        const uint32_t aHiS = sb + (uint32_t)(0 * TILE_E + s * TILE_E) * 2;
        const uint32_t aLoS = sb + (uint32_t)(2 * TILE_E + s * TILE_E) * 2;
        const uint32_t bS   = sb + (uint32_t)(4 * TILE_E + s * TILE_E) * 2;

#pragma unroll
        for (int kk = 0; kk < 2; kk++) {
            uint32_t ahi[4][4], alo[4][4], bf[4][2];
#pragma unroll
            for (int mf = 0; mf < 4; mf++) {
                uint32_t off = (uint32_t)((aRow + mf * 16) * TSTRIDE
                                          + kk * 16 + aKof) * 2;
                ldsm_x4(ahi[mf], aHiS + off);
                ldsm_x4(alo[mf], aLoS + off);
            }
#pragma unroll
            for (int p = 0; p < 2; p++) {
                uint32_t off = (uint32_t)((wn + p * 16 + bRowP) * TSTRIDE
                                          + kk * 16 + bKof) * 2;
                uint32_t r[4];
                ldsm_x4(r, bS + off);
                bf[2 * p][0] = r[0]; bf[2 * p][1] = r[1];
                bf[2 * p + 1][0] = r[2]; bf[2 * p + 1][1] = r[3];
            }
#pragma unroll
            for (int mf = 0; mf < 4; mf++)
#pragma unroll
                for (int nf = 0; nf < 4; nf++) {
                    MMA_F16(acc[mf][nf], ahi[mf], bf[nf][0], bf[nf][1]);
                    MMA_F16(acc[mf][nf], alo[mf], bf[nf][0], bf[nf][1]);
                }
        }
        __syncthreads();
    }

    // ---- epilogue: bias + store + per-group partial stats ----
    const int gid  = lane >> 2;
    const int tid4 = lane & 3;
    const int Cg   = M >> 3;            // channels per group (32 or 128)
    const int ngt  = 128 / Cg;          // groups per m-tile (4 or 1)
    float ps[4] = {0.f, 0.f, 0.f, 0.f};
    float pq[4] = {0.f, 0.f, 0.f, 0.f};
#pragma unroll
    for (int mf = 0; mf < 4; mf++) {
        const int lg = (wm + mf * 16) / Cg;   // local group in tile
        const int m = m0 + wm + mf * 16 + gid;
        const float bm0 = bias[m];
        const float bm8 = bias[m + 8];
        float* y0 = Yb + (size_t)m * NPT;
        float* y8 = Yb + (size_t)(m + 8) * NPT;
#pragma unroll
        for (int nf = 0; nf < 4; nf++) {
            const int n = n0 + wn + nf * 8 + 2 * tid4;
            float a0 = acc[mf][nf][0] + bm0, a1 = acc[mf][nf][1] + bm0;
            float a2 = acc[mf][nf][2] + bm8, a3 = acc[mf][nf][3] + bm8;
            *reinterpret_cast<float2*>(y0 + n) = make_float2(a0, a1);
            *reinterpret_cast<float2*>(y8 + n) = make_float2(a2, a3);
            ps[lg] += a0 + a1 + a2 + a3;
            pq[lg] += a0 * a0 + a1 * a1 + a2 * a2 + a3 * a3;
        }
    }
    // warp shuffle reduce (fixed order, deterministic)
#pragma unroll
    for (int g = 0; g < 4; g++)
#pragma unroll
        for (int o = 16; o > 0; o >>= 1) {
            ps[g] += __shfl_xor_sync(0xFFFFFFFF, ps[g], o);
            pq[g] += __shfl_xor_sync(0xFFFFFFFF, pq[g], o);
        }
    float* red = reinterpret_cast<float*>(smem);   // reuse smem (free now)
    __syncthreads();
    if (lane == 0) {
#pragma unroll
        for (int g = 0; g < 4; g++) {
            red[(g * 8 + wid) * 2 + 0] = ps[g];
            red[(g * 8 + wid) * 2 + 1] = pq[g];
        }
    }
    __syncthreads();
    if (tid < (unsigned)ngt) {
        float s = 0.f, q = 0.f;
        for (int w = 0; w < 8; w++) {
            s += red[(tid * 8 + w) * 2 + 0];
            q += red[(tid * 8 + w) * 2 + 1];
        }
        int bg = b * NGRP + m0 / Cg + tid;
        g_psum[bg * NTILE + blockIdx.x] = s;
        g_psq [bg * NTILE + blockIdx.x] = q;
    }
}

// ---------------- FiLM scale/shift ------------------------------------------
__global__ void scaleshift_kernel(const float* __restrict__ t_emb,
                                  const float* __restrict__ c_emb,
                                  const float* __restrict__ tw,
                                  const float* __restrict__ tb,
                                  const float* __restrict__ cw,
                                  const float* __restrict__ cb) {
    __shared__ float te[C_OUT], ce[C_OUT];
    const int b = blockIdx.x;
    const int c = threadIdx.x;
    te[c] = t_emb[b * C_OUT + c];
    ce[c] = c_emb[b * C_OUT + c];
    __syncthreads();
    float sc = tb[c] + cb[c];
    float sh = tb[c + C_OUT] + cb[c + C_OUT];
    const float* twr_s = tw + (size_t)c * C_OUT;
    const float* twr_h = tw + (size_t)(c + C_OUT) * C_OUT;
    const float* cwr_s = cw + (size_t)c * C_OUT;
    const float* cwr_h = cw + (size_t)(c + C_OUT) * C_OUT;
    for (int k = 0; k < C_OUT; k++) {
        sc += te[k] * twr_s[k] + ce[k] * cwr_s[k];
        sh += te[k] * twr_h[k] + ce[k] * cwr_h[k];
    }
    g_scale[b * C_OUT + c] = sc;
    g_shift[b * C_OUT + c] = sh;
}

// ---------------- final: GN(h2)*(1+scale)+shift+identity --------------------
__global__ void final_kernel(const float* __restrict__ g2w,
                             const float* __restrict__ g2b,
                             float* __restrict__ out) {
    const size_t i = (size_t)blockIdx.x * 256 + threadIdx.x;
    const int Cg = C_OUT / NGRP;
    const int c  = (int)((i / NPT) % C_OUT);
    const int bg = (int)(i / ((size_t)Cg * NPT));
    const int bc = (int)(i / NPT);
    const float m = g_stats[bg * 2 + 0];
    const float r = g_stats[bg * 2 + 1];
    float h = (g_h2[i] - m) * r * g2w[c] + g2b[c];
    out[i] = h * (1.f + g_scale[bc]) + g_shift[bc] + g_x[i];
}

// ======================= launch =============================================
extern "C" void kernel_launch(void* const* d_in, const int* in_sizes, int n_in,
                              void* d_out, int out_size) {
    const float* xyz1    = (const float*)d_in[0];
    const float* points1 = (const float*)d_in[1];
    const float* xyz2    = (const float*)d_in[2];
    const float* points2 = (const float*)d_in[3];
    const float* t_emb   = (const float*)d_in[4];
    const float* c_emb   = (const float*)d_in[5];
    const float* mlp_w   = (const float*)d_in[6];
    const float* mlp_b   = (const float*)d_in[7];
    const float* mlp_gw  = (const float*)d_in[8];
    const float* mlp_gb  = (const float*)d_in[9];
    const float* c1w     = (const float*)d_in[10];
    const float* c1b     = (const float*)d_in[11];
    const float* g1w     = (const float*)d_in[12];
    const float* g1b     = (const float*)d_in[13];
    const float* c2w     = (const float*)d_in[14];
    const float* c2b     = (const float*)d_in[15];
    const float* g2w     = (const float*)d_in[16];
    const float* g2b     = (const float*)d_in[17];
    const float* tw      = (const float*)d_in[18];
    const float* tb      = (const float*)d_in[19];
    const float* cw      = (const float*)d_in[20];
    const float* cb      = (const float*)d_in[21];
    float* out = (float*)d_out;

    cudaFuncSetAttribute(gemm_mma_kernel,
                         cudaFuncAttributeMaxDynamicSharedMemorySize,
                         GEMM_SMEM_BYTES);

    float *p_np, *p_x, *p_h1, *p_h2, *p_stats;
    cudaGetSymbolAddress((void**)&p_np, g_np);
    cudaGetSymbolAddress((void**)&p_x, g_x);
    cudaGetSymbolAddress((void**)&p_h1, g_h1);
    cudaGetSymbolAddress((void**)&p_h2, g_h2);
    cudaGetSymbolAddress((void**)&p_stats, g_stats);
    __half *pWnpHi, *pWnpLo, *pW1Hi, *pW1Lo, *pW2Hi, *pW2Lo;
    __half *pXtNp, *pXtX, *pXtH1;
    cudaGetSymbolAddress((void**)&pWnpHi, g_WnpHi);
    cudaGetSymbolAddress((void**)&pWnpLo, g_WnpLo);
    cudaGetSymbolAddress((void**)&pW1Hi, g_W1Hi);
    cudaGetSymbolAddress((void**)&pW1Lo, g_W1Lo);
    cudaGetSymbolAddress((void**)&pW2Hi, g_W2Hi);
    cudaGetSymbolAddress((void**)&pW2Lo, g_W2Lo);
    cudaGetSymbolAddress((void**)&pXtNp, g_XtNp);
    cudaGetSymbolAddress((void**)&pXtX, g_XtX);
    cudaGetSymbolAddress((void**)&pXtH1, g_XtH1);

    // 1) independent prep
    knn3_kernel<<<dim3(NPT / 256, NB), 256>>>(xyz1, xyz2);
    build_np_kernel<<<NB * C_NP, 256>>>(points1, points2);
    scaleshift_kernel<<<NB, 256>>>(t_emb, c_emb, tw, tb, cw, cb);
    wsplit_kernel<<<(C_OUT * C_NP + 255) / 256, 256>>>(mlp_w, pWnpHi, pWnpLo, C_OUT * C_NP);
    wsplit_kernel<<<(C_E * C_OUT + 255) / 256, 256>>>(c1w, pW1Hi, pW1Lo, C_E * C_OUT);
    wsplit_kernel<<<(C_OUT * C_E + 255) / 256, 256>>>(c2w, pW2Hi, pW2Lo, C_OUT * C_E);

    // 2) np -> transposed fp16 (no GN)
    tsplit_kernel<<<dim3(NPT / 32, C_NP / 32, NB), dim3(32, 8)>>>(
        p_np, pXtNp, nullptr, nullptr, nullptr, nullptr, C_NP, 0);

    // 3) GEMM1 (+fused stats): x_raw = mlp_w @ np + mlp_b
    gemm_mma_kernel<<<dim3(NTILE, C_OUT / 128, NB), 256, GEMM_SMEM_BYTES>>>(
        pWnpHi, pWnpLo, pXtNp, mlp_b, p_x, C_OUT, C_NP);
    gn_fin_kernel<<<1, 128>>>(C_OUT);

    // 4) x = silu(gn(x_raw)); fp32 writeback + transposed fp16
    tsplit_kernel<<<dim3(NPT / 32, C_OUT / 32, NB), dim3(32, 8)>>>(
        p_x, pXtX, p_x, mlp_gw, mlp_gb, p_stats, C_OUT, 1);

    // 5) GEMM2 (+stats): h1_raw = c1w @ x + c1b
    gemm_mma_kernel<<<dim3(NTILE, C_E / 128, NB), 256, GEMM_SMEM_BYTES>>>(
        pW1Hi, pW1Lo, pXtX, c1b, p_h1, C_E, C_OUT);
    gn_fin_kernel<<<1, 128>>>(C_E);

    // 6) h = silu(gn(h1_raw)); transposed fp16
    tsplit_kernel<<<dim3(NPT / 32, C_E / 32, NB), dim3(32, 8)>>>(
        p_h1, pXtH1, nullptr, g1w, g1b, p_stats, C_E, 1);

    // 7) GEMM3 (+stats): h2_raw = c2w @ h + c2b
    gemm_mma_kernel<<<dim3(NTILE, C_OUT / 128, NB), 256, GEMM_SMEM_BYTES>>>(
        pW2Hi, pW2Lo, pXtH1, c2b, p_h2, C_OUT, C_E);
    gn_fin_kernel<<<1, 128>>>(C_OUT);

    // 8) out = gn(h2)*(1+scale) + shift + x
    final_kernel<<<(int)(((size_t)NB * C_OUT * NPT) / 256), 256>>>(g2w, g2b, out);
}

// round 10
// speedup vs baseline: 2.9185x; 1.1387x over previous
#include <cuda_runtime.h>
#include <cuda_fp16.h>
#include <cstdint>
#include <math.h>

#define NB     8
#define NPT    8192
#define SPT    2048
#define C_IN   256
#define C_SKIP 128
#define C_NP   384
#define C_OUT  256
#define C_E    1024
#define NGRP   8
#define NTILE  (NPT / 128)   // 64 n-tiles per GEMM

// ---------------- scratch (device globals; no allocation allowed) -----------
static __device__ float  g_np[(size_t)NB * C_NP * NPT];
static __device__ __half g_xh [(size_t)NB * C_OUT * NPT];  // x_raw fp16
static __device__ __half g_h1h[(size_t)NB * C_E * NPT];    // h1_raw fp16
static __device__ float  g_h2[(size_t)NB * C_OUT * NPT];   // h2_raw fp32
static __device__ float g_w3[(size_t)NB * NPT * 3];
static __device__ int   g_i3[(size_t)NB * NPT * 3];
static __device__ float g_psum[NB * NGRP * NTILE];
static __device__ float g_psq [NB * NGRP * NTILE];
static __device__ float g_stats[NB * NGRP * 2];
static __device__ float g_scale[NB * C_OUT];
static __device__ float g_shift[NB * C_OUT];

// transposed fp16 operands: Xt[b][n][k], k contiguous
static __device__ __half g_XtNp[(size_t)NB * NPT * C_NP];
static __device__ __half g_XtX [(size_t)NB * NPT * C_OUT];
static __device__ __half g_XtH1[(size_t)NB * NPT * C_E];

// weight splits fp16 hi/lo, [M,K] K-contiguous
static __device__ __half g_WnpHi[C_OUT * C_NP], g_WnpLo[C_OUT * C_NP];
static __device__ __half g_W1Hi [C_E * C_OUT],  g_W1Lo [C_E * C_OUT];
static __device__ __half g_W2Hi [C_OUT * C_E],  g_W2Lo [C_OUT * C_E];

__device__ __forceinline__ uint32_t smem_u32(const void* p) {
    uint32_t a;
    asm("{ .reg .u64 t; cvta.to.shared.u64 t, %1; cvt.u32.u64 %0, t; }"
        : "=r"(a) : "l"(p));
    return a;
}

// ======================= 3-NN + weights =====================================
__global__ void knn3_kernel(const float* __restrict__ xyz1,
                            const float* __restrict__ xyz2) {
    __shared__ float sx[SPT], sy[SPT], sz[SPT], sq[SPT];
    const int b = blockIdx.y;
    const float* x2 = xyz2 + (size_t)b * 3 * SPT;
    for (int s = threadIdx.x; s < SPT; s += blockDim.x) {
        float qx = x2[s], qy = x2[SPT + s], qz = x2[2 * SPT + s];
        sx[s] = qx; sy[s] = qy; sz[s] = qz;
        sq[s] = qx * qx + qy * qy + qz * qz;
    }
    __syncthreads();
    const int n = blockIdx.x * blockDim.x + threadIdx.x;
    const float* x1 = xyz1 + (size_t)b * 3 * NPT;
    const float px = x1[n], py = x1[NPT + n], pz = x1[2 * NPT + n];
    const float pn = px * px + py * py + pz * pz;
    float d0 = 3.4e38f, d1 = 3.4e38f, d2 = 3.4e38f;
    int   i0 = 0, i1 = 0, i2 = 0;
    for (int s = 0; s < SPT; s++) {
        float d = -2.f * (px * sx[s] + py * sy[s] + pz * sz[s]) + pn + sq[s];
        if (d < d0)      { d2 = d1; i2 = i1; d1 = d0; i1 = i0; d0 = d; i0 = s; }
        else if (d < d1) { d2 = d1; i2 = i1; d1 = d;  i1 = s; }
        else if (d < d2) { d2 = d;  i2 = s; }
    }
    float r0 = 1.f / (d0 + 1e-8f);
    float r1 = 1.f / (d1 + 1e-8f);
    float r2 = 1.f / (d2 + 1e-8f);
    float inv = 1.f / (r0 + r1 + r2);
    size_t o = ((size_t)b * NPT + n) * 3;
    g_w3[o + 0] = r0 * inv; g_w3[o + 1] = r1 * inv; g_w3[o + 2] = r2 * inv;
    g_i3[o + 0] = i0;       g_i3[o + 1] = i1;       g_i3[o + 2] = i2;
}

// ---------------- build new_points fp32 -------------------------------------
__global__ void build_np_kernel(const float* __restrict__ points1,
                                const float* __restrict__ points2) {
    const int bc = blockIdx.x;
    const int b = bc / C_NP;
    const int c = bc % C_NP;
    float* dst = g_np + ((size_t)b * C_NP + c) * NPT;
    if (c < C_SKIP) {
        const float* src = points1 + ((size_t)b * C_SKIP + c) * NPT;
        for (int n = threadIdx.x; n < NPT; n += blockDim.x) dst[n] = src[n];
    } else {
        __shared__ float row[SPT];
        const float* src = points2 + ((size_t)b * C_IN + (c - C_SKIP)) * SPT;
        for (int s = threadIdx.x; s < SPT; s += blockDim.x) row[s] = src[s];
        __syncthreads();
        for (int n = threadIdx.x; n < NPT; n += blockDim.x) {
            size_t o = ((size_t)b * NPT + n) * 3;
            dst[n] = g_w3[o + 0] * row[g_i3[o + 0]]
                   + g_w3[o + 1] * row[g_i3[o + 1]]
                   + g_w3[o + 2] * row[g_i3[o + 2]];
        }
    }
}

// ---------------- weight split to fp16 hi/lo --------------------------------
__global__ void wsplit_kernel(const float* __restrict__ w,
                              __half* __restrict__ hi,
                              __half* __restrict__ lo, int n) {
    int i = blockIdx.x * 256 + threadIdx.x;
    if (i < n) {
        float v = w[i];
        __half h = __float2half(v);
        hi[i] = h;
        lo[i] = __float2half(v - __half2float(h));
    }
}

// ---------------- fused (GN+SiLU)? + transpose + fp16 convert ---------------
// src fp32 OR fp16 (one non-null): [B,C,NPT].  dst: [B,NPT,C] fp16.
__global__ void tsplit_kernel(const float* __restrict__ srcF,
                              const __half* __restrict__ srcH,
                              __half* __restrict__ dst,
                              const float* __restrict__ gw,
                              const float* __restrict__ gb,
                              const float* __restrict__ stats,
                              int C, int mode) {
    __shared__ float s[32][33];
    const int b = blockIdx.z;
    const int n = blockIdx.x * 32 + threadIdx.x;
    const int Cg = C / NGRP;
#pragma unroll
    for (int i = 0; i < 4; i++) {
        int c = blockIdx.y * 32 + threadIdx.y + i * 8;
        size_t idx = ((size_t)b * C + c) * NPT + n;
        float v = srcF ? srcF[idx] : __half2float(srcH[idx]);
        if (mode) {
            int bg = b * NGRP + c / Cg;
            float m = stats[bg * 2 + 0];
            float r = stats[bg * 2 + 1];
            v = (v - m) * r * gw[c] + gb[c];
            v = v * (1.f / (1.f + expf(-v)));          // SiLU
        }
        s[threadIdx.y + i * 8][threadIdx.x] = v;
    }
    __syncthreads();
    const int cg = blockIdx.y * 32 + threadIdx.x;
#pragma unroll
    for (int i = 0; i < 4; i++) {
        int n2 = blockIdx.x * 32 + threadIdx.y + i * 8;
        float v = s[threadIdx.x][threadIdx.y + i * 8];
        dst[((size_t)b * NPT + n2) * C + cg] = __float2half(v);
    }
}

// ---------------- GN finalize: sum 64 per-tile partials ---------------------
__global__ void gn_fin_kernel(int C) {
    int bg = threadIdx.x;
    if (bg < NB * NGRP) {
        float sm = 0.f, sq = 0.f;
        for (int t = 0; t < NTILE; t++) {
            sm += g_psum[bg * NTILE + t];
            sq += g_psq [bg * NTILE + t];
        }
        float cnt = (float)((size_t)(C / NGRP) * NPT);
        float m = sm / cnt;
        float var = sq / cnt - m * m;
        g_stats[bg * 2 + 0] = m;
        g_stats[bg * 2 + 1] = rsqrtf(var + 1e-5f);
    }
}

// ======================= mma.sync fp16 split-W GEMM + fused stats ===========
// CTA 128x128x32, 256 thr (8 warps 2x4), warp tile 64x32, 2 MMAs/frag.
// Output: Yf fp32 OR Yh fp16 (one non-null). Epilogue emits GN partials.
#define TSTRIDE 40
#define TILE_E  (128 * TSTRIDE)
#define GEMM_SMEM_BYTES (6 * TILE_E * 2)  // 61440 B

__device__ __forceinline__ void cp16(uint32_t saddr, const void* gaddr) {
    asm volatile("cp.async.cg.shared.global [%0], [%1], 16;"
                 :: "r"(saddr), "l"(gaddr));
}
__device__ __forceinline__ void ldsm_x4(uint32_t* r, uint32_t addr) {
    asm volatile("ldmatrix.sync.aligned.m8n8.x4.shared.b16 {%0,%1,%2,%3}, [%4];"
                 : "=r"(r[0]), "=r"(r[1]), "=r"(r[2]), "=r"(r[3]) : "r"(addr));
}
#define MMA_F16(ac, a, b0, b1)                                                \
    asm volatile("mma.sync.aligned.m16n8k16.row.col.f32.f16.f16.f32 "         \
                 "{%0,%1,%2,%3}, {%4,%5,%6,%7}, {%8,%9}, {%0,%1,%2,%3};"      \
                 : "+f"((ac)[0]), "+f"((ac)[1]), "+f"((ac)[2]), "+f"((ac)[3]) \
                 : "r"((a)[0]), "r"((a)[1]), "r"((a)[2]), "r"((a)[3]),        \
                   "r"(b0), "r"(b1))

__global__ void __launch_bounds__(256, 2)
gemm_mma_kernel(const __half* __restrict__ Whi,
                const __half* __restrict__ Wlo,
                const __half* __restrict__ X,
                const float* __restrict__ bias,
                float* __restrict__ Yf,
                __half* __restrict__ Yh,
                int M, int K) {
    extern __shared__ __half smem[];
    const uint32_t sb = smem_u32(smem);
    const int tid  = threadIdx.x;
    const int wid  = tid >> 5;
    const int lane = tid & 31;

    const int n0 = blockIdx.x * 128;
    const int m0 = blockIdx.y * 128;
    const int b  = blockIdx.z;
    const __half* XB = X + (size_t)b * NPT * K;

    const int wm = (wid >> 2) * 64;
    const int wn = (wid & 3) * 32;

    float acc[4][4][4];
#pragma unroll
    for (int i = 0; i < 4; i++)
#pragma unroll
        for (int j = 0; j < 4; j++)
#pragma unroll
            for (int q = 0; q < 4; q++) acc[i][j][q] = 0.f;

    const int row0 = tid >> 2,         seg0 = tid & 3;
    const int row1 = (tid + 256) >> 2, seg1 = (tid + 256) & 3;

    const int niter = K >> 5;

    auto load_stage = [&](int s, int k0) {
        const uint32_t aHiS = sb + (uint32_t)(0 * TILE_E + s * TILE_E) * 2;
        const uint32_t aLoS = sb + (uint32_t)(2 * TILE_E + s * TILE_E) * 2;
        const uint32_t bS   = sb + (uint32_t)(4 * TILE_E + s * TILE_E) * 2;
        {
            uint32_t so = (uint32_t)(row0 * TSTRIDE + seg0 * 8) * 2;
            size_t ga = (size_t)(m0 + row0) * K + k0 + seg0 * 8;
            size_t gb = (size_t)(n0 + row0) * K + k0 + seg0 * 8;
            cp16(aHiS + so, Whi + ga);
            cp16(aLoS + so, Wlo + ga);
            cp16(bS + so, XB + gb);
        }
        {
            uint32_t so = (uint32_t)(row1 * TSTRIDE + seg1 * 8) * 2;
            size_t ga = (size_t)(m0 + row1) * K + k0 + seg1 * 8;
            size_t gb = (size_t)(n0 + row1) * K + k0 + seg1 * 8;
            cp16(aHiS + so, Whi + ga);
            cp16(aLoS + so, Wlo + ga);
            cp16(bS + so, XB + gb);
        }
        asm volatile("cp.async.commit_group;" ::: "memory");
    };

    const int aRow = wm + (lane & 15);
    const int aKof = (lane >> 4) * 8;
    const int bRowP = ((lane >> 4) ? 8 : 0) + (lane & 7);
    const int bKof  = ((lane >> 3) & 1) * 8;

    load_stage(0, 0);

    for (int it = 0; it < niter; it++) {
        if (it + 1 < niter) {
            load_stage((it + 1) & 1, (it + 1) << 5);
            asm volatile("cp.async.wait_group 1;" ::: "memory");
        } else {
            asm volatile("cp.async.wait_group 0;" ::: "memory");
        }
        __syncthreads();

        const int s = it & 1;
        const uint32_t aHiS = sb + (uint32_t)(0 * TILE_E + s * TILE_E) * 2;
        const uint32_t aLoS = sb + (uint32_t)(2 * TILE_E + s * TILE_E) * 2;
        const uint32_t bS   = sb + (uint32_t)(4 * TILE_E + s * TILE_E) * 2;

#pragma unroll
        for (int kk = 0; kk < 2; kk++) {
            uint32_t ahi[4][4], alo[4][4], bf[4][2];
#pragma unroll
            for (int mf = 0; mf < 4; mf++) {
                uint32_t off = (uint32_t)((aRow + mf * 16) * TSTRIDE
                                          + kk * 16 + aKof) * 2;
                ldsm_x4(ahi[mf], aHiS + off);
                ldsm_x4(alo[mf], aLoS + off);
            }
#pragma unroll
            for (int p = 0; p < 2; p++) {
                uint32_t off = (uint32_t)((wn + p * 16 + bRowP) * TSTRIDE
                                          + kk * 16 + bKof) * 2;
                uint32_t r[4];
                ldsm_x4(r, bS + off);
                bf[2 * p][0] = r[0]; bf[2 * p][1] = r[1];
                bf[2 * p + 1][0] = r[2]; bf[2 * p + 1][1] = r[3];
            }
#pragma unroll
            for (int mf = 0; mf < 4; mf++)
#pragma unroll
                for (int nf = 0; nf < 4; nf++) {
                    MMA_F16(acc[mf][nf], ahi[mf], bf[nf][0], bf[nf][1]);
                    MMA_F16(acc[mf][nf], alo[mf], bf[nf][0], bf[nf][1]);
                }
        }
        __syncthreads();
    }

    // ---- epilogue: bias + store (fp32 or fp16) + per-group partial stats ---
    const int gid  = lane >> 2;
    const int tid4 = lane & 3;
    const int Cg   = M >> 3;
    const int ngt  = 128 / Cg;
    float ps[4] = {0.f, 0.f, 0.f, 0.f};
    float pq[4] = {0.f, 0.f, 0.f, 0.f};
#pragma unroll
    for (int mf = 0; mf < 4; mf++) {
        const int lg = (wm + mf * 16) / Cg;
        const int m = m0 + wm + mf * 16 + gid;
        const float bm0 = bias[m];
        const float bm8 = bias[m + 8];
#pragma unroll
        for (int nf = 0; nf < 4; nf++) {
            const int n = n0 + wn + nf * 8 + 2 * tid4;
            float a0 = acc[mf][nf][0] + bm0, a1 = acc[mf][nf][1] + bm0;
            float a2 = acc[mf][nf][2] + bm8, a3 = acc[mf][nf][3] + bm8;
            if (Yf) {
                float* y0 = Yf + ((size_t)b * M + m) * NPT + n;
                float* y8 = Yf + ((size_t)b * M + m + 8) * NPT + n;
                *reinterpret_cast<float2*>(y0) = make_float2(a0, a1);
                *reinterpret_cast<float2*>(y8) = make_float2(a2, a3);
            } else {
                __half* y0 = Yh + ((size_t)b * M + m) * NPT + n;
                __half* y8 = Yh + ((size_t)b * M + m + 8) * NPT + n;
                *reinterpret_cast<__half2*>(y0) = __floats2half2_rn(a0, a1);
                *reinterpret_cast<__half2*>(y8) = __floats2half2_rn(a2, a3);
            }
            ps[lg] += a0 + a1 + a2 + a3;
            pq[lg] += a0 * a0 + a1 * a1 + a2 * a2 + a3 * a3;
        }
    }
#pragma unroll
    for (int g = 0; g < 4; g++)
#pragma unroll
        for (int o = 16; o > 0; o >>= 1) {
            ps[g] += __shfl_xor_sync(0xFFFFFFFF, ps[g], o);
            pq[g] += __shfl_xor_sync(0xFFFFFFFF, pq[g], o);
        }
    float* red = reinterpret_cast<float*>(smem);
    __syncthreads();
    if (lane == 0) {
#pragma unroll
        for (int g = 0; g < 4; g++) {
            red[(g * 8 + wid) * 2 + 0] = ps[g];
            red[(g * 8 + wid) * 2 + 1] = pq[g];
        }
    }
    __syncthreads();
    if (tid < (unsigned)ngt) {
        float s = 0.f, q = 0.f;
        for (int w = 0; w < 8; w++) {
            s += red[(tid * 8 + w) * 2 + 0];
            q += red[(tid * 8 + w) * 2 + 1];
        }
        int bg = b * NGRP + m0 / Cg + tid;
        g_psum[bg * NTILE + blockIdx.x] = s;
        g_psq [bg * NTILE + blockIdx.x] = q;
    }
}

// ---------------- FiLM scale/shift ------------------------------------------
__global__ void scaleshift_kernel(const float* __restrict__ t_emb,
                                  const float* __restrict__ c_emb,
                                  const float* __restrict__ tw,
                                  const float* __restrict__ tb,
                                  const float* __restrict__ cw,
                                  const float* __restrict__ cb) {
    __shared__ float te[C_OUT], ce[C_OUT];
    const int b = blockIdx.x;
    const int c = threadIdx.x;
    te[c] = t_emb[b * C_OUT + c];
    ce[c] = c_emb[b * C_OUT + c];
    __syncthreads();
    float sc = tb[c] + cb[c];
    float sh = tb[c + C_OUT] + cb[c + C_OUT];
    const float* twr_s = tw + (size_t)c * C_OUT;
    const float* twr_h = tw + (size_t)(c + C_OUT) * C_OUT;
    const float* cwr_s = cw + (size_t)c * C_OUT;
    const float* cwr_h = cw + (size_t)(c + C_OUT) * C_OUT;
    for (int k = 0; k < C_OUT; k++) {
        sc += te[k] * twr_s[k] + ce[k] * cwr_s[k];
        sh += te[k] * twr_h[k] + ce[k] * cwr_h[k];
    }
    g_scale[b * C_OUT + c] = sc;
    g_shift[b * C_OUT + c] = sh;
}

// -------- final: out = GN(h2)*(1+scale)+shift + identity(from XtX) ----------
// Tile-transpose: identity = XtX[b][n][c] (fp16, transposed layout).
__global__ void final_kernel(const float* __restrict__ g2w,
                             const float* __restrict__ g2b,
                             float* __restrict__ out) {
    __shared__ float s[32][33];
    const int b = blockIdx.z;
    // load identity tile (coalesced over c)
#pragma unroll
    for (int i = 0; i < 4; i++) {
        int n = blockIdx.x * 32 + threadIdx.y + i * 8;
        int c = blockIdx.y * 32 + threadIdx.x;
        s[threadIdx.y + i * 8][threadIdx.x] =
            __half2float(g_XtX[((size_t)b * NPT + n) * C_OUT + c]);
    }
    __syncthreads();
    const int n = blockIdx.x * 32 + threadIdx.x;
    const int Cg = C_OUT / NGRP;
#pragma unroll
    for (int i = 0; i < 4; i++) {
        int c = blockIdx.y * 32 + threadIdx.y + i * 8;
        size_t idx = ((size_t)b * C_OUT + c) * NPT + n;
        int bg = b * NGRP + c / Cg;
        float m = g_stats[bg * 2 + 0];
        float r = g_stats[bg * 2 + 1];
        float h = (g_h2[idx] - m) * r * g2w[c] + g2b[c];
        float id = s[threadIdx.x][threadIdx.y + i * 8];
        out[idx] = h * (1.f + g_scale[b * C_OUT + c])
                 + g_shift[b * C_OUT + c] + id;
    }
}

// ======================= launch =============================================
extern "C" void kernel_launch(void* const* d_in, const int* in_sizes, int n_in,
                              void* d_out, int out_size) {
    const float* xyz1    = (const float*)d_in[0];
    const float* points1 = (const float*)d_in[1];
    const float* xyz2    = (const float*)d_in[2];
    const float* points2 = (const float*)d_in[3];
    const float* t_emb   = (const float*)d_in[4];
    const float* c_emb   = (const float*)d_in[5];
    const float* mlp_w   = (const float*)d_in[6];
    const float* mlp_b   = (const float*)d_in[7];
    const float* mlp_gw  = (const float*)d_in[8];
    const float* mlp_gb  = (const float*)d_in[9];
    const float* c1w     = (const float*)d_in[10];
    const float* c1b     = (const float*)d_in[11];
    const float* g1w     = (const float*)d_in[12];
    const float* g1b     = (const float*)d_in[13];
    const float* c2w     = (const float*)d_in[14];
    const float* c2b     = (const float*)d_in[15];
    const float* g2w     = (const float*)d_in[16];
    const float* g2b     = (const float*)d_in[17];
    const float* tw      = (const float*)d_in[18];
    const float* tb      = (const float*)d_in[19];
    const float* cw      = (const float*)d_in[20];
    const float* cb      = (const float*)d_in[21];
    float* out = (float*)d_out;

    cudaFuncSetAttribute(gemm_mma_kernel,
                         cudaFuncAttributeMaxDynamicSharedMemorySize,
                         GEMM_SMEM_BYTES);

    float *p_np, *p_h2, *p_stats;
    cudaGetSymbolAddress((void**)&p_np, g_np);
    cudaGetSymbolAddress((void**)&p_h2, g_h2);
    cudaGetSymbolAddress((void**)&p_stats, g_stats);
    __half *p_xh, *p_h1h;
    cudaGetSymbolAddress((void**)&p_xh, g_xh);
    cudaGetSymbolAddress((void**)&p_h1h, g_h1h);
    __half *pWnpHi, *pWnpLo, *pW1Hi, *pW1Lo, *pW2Hi, *pW2Lo;
    __half *pXtNp, *pXtX, *pXtH1;
    cudaGetSymbolAddress((void**)&pWnpHi, g_WnpHi);
    cudaGetSymbolAddress((void**)&pWnpLo, g_WnpLo);
    cudaGetSymbolAddress((void**)&pW1Hi, g_W1Hi);
    cudaGetSymbolAddress((void**)&pW1Lo, g_W1Lo);
    cudaGetSymbolAddress((void**)&pW2Hi, g_W2Hi);
    cudaGetSymbolAddress((void**)&pW2Lo, g_W2Lo);
    cudaGetSymbolAddress((void**)&pXtNp, g_XtNp);
    cudaGetSymbolAddress((void**)&pXtX, g_XtX);
    cudaGetSymbolAddress((void**)&pXtH1, g_XtH1);

    // 1) independent prep
    knn3_kernel<<<dim3(NPT / 256, NB), 256>>>(xyz1, xyz2);
    build_np_kernel<<<NB * C_NP, 256>>>(points1, points2);
    scaleshift_kernel<<<NB, 256>>>(t_emb, c_emb, tw, tb, cw, cb);
    wsplit_kernel<<<(C_OUT * C_NP + 255) / 256, 256>>>(mlp_w, pWnpHi, pWnpLo, C_OUT * C_NP);
    wsplit_kernel<<<(C_E * C_OUT + 255) / 256, 256>>>(c1w, pW1Hi, pW1Lo, C_E * C_OUT);
    wsplit_kernel<<<(C_OUT * C_E + 255) / 256, 256>>>(c2w, pW2Hi, pW2Lo, C_OUT * C_E);

    // 2) np -> transposed fp16 (no GN)
    tsplit_kernel<<<dim3(NPT / 32, C_NP / 32, NB), dim3(32, 8)>>>(
        p_np, nullptr, pXtNp, nullptr, nullptr, nullptr, C_NP, 0);

    // 3) GEMM1 (+stats): x_raw(fp16) = mlp_w @ np + mlp_b
    gemm_mma_kernel<<<dim3(NTILE, C_OUT / 128, NB), 256, GEMM_SMEM_BYTES>>>(
        pWnpHi, pWnpLo, pXtNp, mlp_b, nullptr, p_xh, C_OUT, C_NP);
    gn_fin_kernel<<<1, 128>>>(C_OUT);

    // 4) XtX = transpose(silu(gn(x_raw)))
    tsplit_kernel<<<dim3(NPT / 32, C_OUT / 32, NB), dim3(32, 8)>>>(
        nullptr, p_xh, pXtX, mlp_gw, mlp_gb, p_stats, C_OUT, 1);

    // 5) GEMM2 (+stats): h1_raw(fp16) = c1w @ x + c1b
    gemm_mma_kernel<<<dim3(NTILE, C_E / 128, NB), 256, GEMM_SMEM_BYTES>>>(
        pW1Hi, pW1Lo, pXtX, c1b, nullptr, p_h1h, C_E, C_OUT);
    gn_fin_kernel<<<1, 128>>>(C_E);

    // 6) XtH1 = transpose(silu(gn(h1_raw)))
    tsplit_kernel<<<dim3(NPT / 32, C_E / 32, NB), dim3(32, 8)>>>(
        nullptr, p_h1h, pXtH1, g1w, g1b, p_stats, C_E, 1);

    // 7) GEMM3 (+stats): h2_raw(fp32) = c2w @ h + c2b
    gemm_mma_kernel<<<dim3(NTILE, C_OUT / 128, NB), 256, GEMM_SMEM_BYTES>>>(
        pW2Hi, pW2Lo, pXtH1, c2b, p_h2, nullptr, C_OUT, C_E);
    gn_fin_kernel<<<1, 128>>>(C_OUT);

    // 8) out = gn(h2)*(1+scale) + shift + identity(XtX)
    final_kernel<<<dim3(NPT / 32, C_OUT / 32, NB), dim3(32, 8)>>>(g2w, g2b, out);
}

// round 11
// speedup vs baseline: 4.3453x; 1.4889x over previous
#include <cuda_runtime.h>
#include <cuda_fp16.h>
#include <cstdint>
#include <math.h>

#define NB     8
#define NPT    8192
#define SPT    2048
#define C_IN   256
#define C_SKIP 128
#define C_NP   384
#define C_OUT  256
#define C_E    1024
#define NGRP   8
#define NTILE  (NPT / 128)   // 64 n-tiles per GEMM

// ---------------- scratch (device globals; no allocation allowed) -----------
static __device__ __half g_nph[(size_t)NB * C_NP * NPT];   // new_points fp16 [C,N]
static __device__ __half g_xh [(size_t)NB * C_OUT * NPT];  // x raw -> normalized in place
static __device__ __half g_h1h[(size_t)NB * C_E * NPT];    // h1 raw -> normalized in place
static __device__ float  g_h2 [(size_t)NB * C_OUT * NPT];  // h2 raw fp32
static __device__ float g_w3[(size_t)NB * NPT * 3];
static __device__ int   g_i3[(size_t)NB * NPT * 3];
static __device__ float g_psum[NB * NGRP * NTILE];
static __device__ float g_psq [NB * NGRP * NTILE];
static __device__ float g_stats[NB * NGRP * 2];
static __device__ float g_scale[NB * C_OUT];
static __device__ float g_shift[NB * C_OUT];

// fp16 weights [M,K] K-contiguous (single, unsplit)
static __device__ __half g_Wnp[C_OUT * C_NP];
static __device__ __half g_W1 [C_E * C_OUT];
static __device__ __half g_W2 [C_OUT * C_E];

__device__ __forceinline__ uint32_t smem_u32(const void* p) {
    uint32_t a;
    asm("{ .reg .u64 t; cvta.to.shared.u64 t, %1; cvt.u32.u64 %0, t; }"
        : "=r"(a) : "l"(p));
    return a;
}

// ======================= 3-NN + weights =====================================
__global__ void knn3_kernel(const float* __restrict__ xyz1,
                            const float* __restrict__ xyz2) {
    __shared__ float sx[SPT], sy[SPT], sz[SPT], sq[SPT];
    const int b = blockIdx.y;
    const float* x2 = xyz2 + (size_t)b * 3 * SPT;
    for (int s = threadIdx.x; s < SPT; s += blockDim.x) {
        float qx = x2[s], qy = x2[SPT + s], qz = x2[2 * SPT + s];
        sx[s] = qx; sy[s] = qy; sz[s] = qz;
        sq[s] = qx * qx + qy * qy + qz * qz;
    }
    __syncthreads();
    const int n = blockIdx.x * blockDim.x + threadIdx.x;
    const float* x1 = xyz1 + (size_t)b * 3 * NPT;
    const float px = x1[n], py = x1[NPT + n], pz = x1[2 * NPT + n];
    const float pn = px * px + py * py + pz * pz;
    float d0 = 3.4e38f, d1 = 3.4e38f, d2 = 3.4e38f;
    int   i0 = 0, i1 = 0, i2 = 0;
    for (int s = 0; s < SPT; s++) {
        float d = -2.f * (px * sx[s] + py * sy[s] + pz * sz[s]) + pn + sq[s];
        if (d < d0)      { d2 = d1; i2 = i1; d1 = d0; i1 = i0; d0 = d; i0 = s; }
        else if (d < d1) { d2 = d1; i2 = i1; d1 = d;  i1 = s; }
        else if (d < d2) { d2 = d;  i2 = s; }
    }
    float r0 = 1.f / (d0 + 1e-8f);
    float r1 = 1.f / (d1 + 1e-8f);
    float r2 = 1.f / (d2 + 1e-8f);
    float inv = 1.f / (r0 + r1 + r2);
    size_t o = ((size_t)b * NPT + n) * 3;
    g_w3[o + 0] = r0 * inv; g_w3[o + 1] = r1 * inv; g_w3[o + 2] = r2 * inv;
    g_i3[o + 0] = i0;       g_i3[o + 1] = i1;       g_i3[o + 2] = i2;
}

// ---------------- build new_points fp16 [C,N] (no transpose needed) ---------
__global__ void build_np_kernel(const float* __restrict__ points1,
                                const float* __restrict__ points2) {
    const int bc = blockIdx.x;
    const int b = bc / C_NP;
    const int c = bc % C_NP;
    __half* dst = g_nph + ((size_t)b * C_NP + c) * NPT;
    if (c < C_SKIP) {
        const float* src = points1 + ((size_t)b * C_SKIP + c) * NPT;
        for (int n = threadIdx.x * 2; n < NPT; n += blockDim.x * 2) {
            float2 v = *reinterpret_cast<const float2*>(src + n);
            *reinterpret_cast<__half2*>(dst + n) = __floats2half2_rn(v.x, v.y);
        }
    } else {
        __shared__ float row[SPT];
        const float* src = points2 + ((size_t)b * C_IN + (c - C_SKIP)) * SPT;
        for (int s = threadIdx.x; s < SPT; s += blockDim.x) row[s] = src[s];
        __syncthreads();
        for (int n = threadIdx.x * 2; n < NPT; n += blockDim.x * 2) {
            size_t o = ((size_t)b * NPT + n) * 3;
            float v0 = g_w3[o + 0] * row[g_i3[o + 0]]
                     + g_w3[o + 1] * row[g_i3[o + 1]]
                     + g_w3[o + 2] * row[g_i3[o + 2]];
            float v1 = g_w3[o + 3] * row[g_i3[o + 3]]
                     + g_w3[o + 4] * row[g_i3[o + 4]]
                     + g_w3[o + 5] * row[g_i3[o + 5]];
            *reinterpret_cast<__half2*>(dst + n) = __floats2half2_rn(v0, v1);
        }
    }
}

// ---------------- weight convert fp32 -> fp16 -------------------------------
__global__ void wconv_kernel(const float* __restrict__ w,
                             __half* __restrict__ o, int n) {
    int i = (blockIdx.x * 256 + threadIdx.x) * 2;
    if (i < n) {
        float2 v = *reinterpret_cast<const float2*>(w + i);
        *reinterpret_cast<__half2*>(o + i) = __floats2half2_rn(v.x, v.y);
    }
}

// ---------------- in-place GN + SiLU (elementwise, [C,N] layout) ------------
__global__ void norm_kernel(__half* __restrict__ x,
                            const float* __restrict__ gw,
                            const float* __restrict__ gb,
                            const float* __restrict__ stats, int C) {
    const size_t i8 = ((size_t)blockIdx.x * 256 + threadIdx.x) * 8;
    const int c  = (int)((i8 / NPT) % C);
    const int bg = (int)(i8 / ((size_t)(C / NGRP) * NPT));
    const float m = stats[bg * 2 + 0];
    const float r = stats[bg * 2 + 1];
    const float sc = r * gw[c];
    const float sh = gb[c] - m * sc;
    uint4 v = *reinterpret_cast<const uint4*>(x + i8);
    __half2* h = reinterpret_cast<__half2*>(&v);
#pragma unroll
    for (int j = 0; j < 4; j++) {
        float2 f = __half22float2(h[j]);
        float a = f.x * sc + sh;
        float b2 = f.y * sc + sh;
        a = a * (1.f / (1.f + expf(-a)));
        b2 = b2 * (1.f / (1.f + expf(-b2)));
        h[j] = __floats2half2_rn(a, b2);
    }
    *reinterpret_cast<uint4*>(x + i8) = v;
}

// ---------------- GN finalize: sum 64 per-tile partials ---------------------
__global__ void gn_fin_kernel(int C) {
    int bg = threadIdx.x;
    if (bg < NB * NGRP) {
        float sm = 0.f, sq = 0.f;
        for (int t = 0; t < NTILE; t++) {
            sm += g_psum[bg * NTILE + t];
            sq += g_psq [bg * NTILE + t];
        }
        float cnt = (float)((size_t)(C / NGRP) * NPT);
        float m = sm / cnt;
        float var = sq / cnt - m * m;
        g_stats[bg * 2 + 0] = m;
        g_stats[bg * 2 + 1] = rsqrtf(var + 1e-5f);
    }
}

// ======================= mma.sync fp16 GEMM (B in natural [K,N] layout) =====
// Y[b](M x 8192) = W(MxK) @ X[b](K x 8192) + bias.
// A = W [M,K] k-major; B = X [K,N] n-major, consumed via ldmatrix.trans.
// CTA 128x128x32, 256 thr (8 warps 2x4), warp tile 64x32, 1 MMA per frag.
#define TSTRIDE 40
#define BSTRIDE 136
#define ATILE   (128 * TSTRIDE)          // 5120 halfs
#define BTILE   (32 * BSTRIDE)           // 4352 halfs
#define STAGE_E (ATILE + BTILE)          // 9472 halfs
#define GEMM_SMEM_BYTES (2 * STAGE_E * 2) // 37888 B

__device__ __forceinline__ void cp16(uint32_t saddr, const void* gaddr) {
    asm volatile("cp.async.cg.shared.global [%0], [%1], 16;"
                 :: "r"(saddr), "l"(gaddr));
}
__device__ __forceinline__ void ldsm_x4(uint32_t* r, uint32_t addr) {
    asm volatile("ldmatrix.sync.aligned.m8n8.x4.shared.b16 {%0,%1,%2,%3}, [%4];"
                 : "=r"(r[0]), "=r"(r[1]), "=r"(r[2]), "=r"(r[3]) : "r"(addr));
}
__device__ __forceinline__ void ldsm_x4_t(uint32_t* r, uint32_t addr) {
    asm volatile("ldmatrix.sync.aligned.m8n8.x4.trans.shared.b16 {%0,%1,%2,%3}, [%4];"
                 : "=r"(r[0]), "=r"(r[1]), "=r"(r[2]), "=r"(r[3]) : "r"(addr));
}
#define MMA_F16(ac, a, b0, b1)                                                \
    asm volatile("mma.sync.aligned.m16n8k16.row.col.f32.f16.f16.f32 "         \
                 "{%0,%1,%2,%3}, {%4,%5,%6,%7}, {%8,%9}, {%0,%1,%2,%3};"      \
                 : "+f"((ac)[0]), "+f"((ac)[1]), "+f"((ac)[2]), "+f"((ac)[3]) \
                 : "r"((a)[0]), "r"((a)[1]), "r"((a)[2]), "r"((a)[3]),        \
                   "r"(b0), "r"(b1))

__global__ void __launch_bounds__(256, 2)
gemm_mma_kernel(const __half* __restrict__ W,
                const __half* __restrict__ X,
                const float* __restrict__ bias,
                float* __restrict__ Yf,
                __half* __restrict__ Yh,
                int M, int K) {
    extern __shared__ __half smem[];
    const uint32_t sb = smem_u32(smem);
    const int tid  = threadIdx.x;
    const int wid  = tid >> 5;
    const int lane = tid & 31;

    const int n0 = blockIdx.x * 128;
    const int m0 = blockIdx.y * 128;
    const int b  = blockIdx.z;
    const __half* XB = X + (size_t)b * K * NPT;   // [K, N] natural layout

    const int wm = (wid >> 2) * 64;
    const int wn = (wid & 3) * 32;

    float acc[4][4][4];
#pragma unroll
    for (int i = 0; i < 4; i++)
#pragma unroll
        for (int j = 0; j < 4; j++)
#pragma unroll
            for (int q = 0; q < 4; q++) acc[i][j][q] = 0.f;

    const int niter = K >> 5;   // BK=32

    auto load_stage = [&](int s, int k0) {
        const uint32_t aS = sb + (uint32_t)(s * STAGE_E) * 2;
        const uint32_t bS = sb + (uint32_t)(s * STAGE_E + ATILE) * 2;
        // A: 512 cp16 units (128 rows x 4 segs), 2 per thread
#pragma unroll
        for (int r = 0; r < 2; r++) {
            int u = tid + r * 256;
            int row = u >> 2, seg = u & 3;
            cp16(aS + (uint32_t)(row * TSTRIDE + seg * 8) * 2,
                 W + (size_t)(m0 + row) * K + k0 + seg * 8);
        }
        // B: 512 cp16 units (32 k-rows x 16 segs), 2 per thread
#pragma unroll
        for (int r = 0; r < 2; r++) {
            int u = tid + r * 256;
            int row = u >> 4, seg = u & 15;
            cp16(bS + (uint32_t)(row * BSTRIDE + seg * 8) * 2,
                 XB + (size_t)(k0 + row) * NPT + n0 + seg * 8);
        }
        asm volatile("cp.async.commit_group;" ::: "memory");
    };

    // A ldmatrix lane mapping (non-trans, K-major rows)
    const int aRow = wm + (lane & 15);
    const int aKof = (lane >> 4) * 8;
    // B ldmatrix.trans lane mapping ([K,N] rows)
    const int bl  = lane & 7;
    const int bg2 = lane >> 3;
    const int bKrow = (bg2 & 1) * 8 + bl;
    const int bNcol = (bg2 >> 1) * 8;

    load_stage(0, 0);

    for (int it = 0; it < niter; it++) {
        if (it + 1 < niter) {
            load_stage((it + 1) & 1, (it + 1) << 5);
            asm volatile("cp.async.wait_group 1;" ::: "memory");
        } else {
            asm volatile("cp.async.wait_group 0;" ::: "memory");
        }
        __syncthreads();

        const int s = it & 1;
        const uint32_t aS = sb + (uint32_t)(s * STAGE_E) * 2;
        const uint32_t bS = sb + (uint32_t)(s * STAGE_E + ATILE) * 2;

#pragma unroll
        for (int kk = 0; kk < 2; kk++) {
            uint32_t af[4][4], bf[4][2];
#pragma unroll
            for (int mf = 0; mf < 4; mf++) {
                uint32_t off = (uint32_t)((aRow + mf * 16) * TSTRIDE
                                          + kk * 16 + aKof) * 2;
                ldsm_x4(af[mf], aS + off);
            }
#pragma unroll
            for (int p = 0; p < 2; p++) {
                uint32_t off = (uint32_t)((kk * 16 + bKrow) * BSTRIDE
                                          + wn + p * 16 + bNcol) * 2;
                uint32_t r[4];
                ldsm_x4_t(r, bS + off);
                bf[2 * p][0] = r[0]; bf[2 * p][1] = r[1];
                bf[2 * p + 1][0] = r[2]; bf[2 * p + 1][1] = r[3];
            }
#pragma unroll
            for (int mf = 0; mf < 4; mf++)
#pragma unroll
                for (int nf = 0; nf < 4; nf++)
                    MMA_F16(acc[mf][nf], af[mf], bf[nf][0], bf[nf][1]);
        }
        __syncthreads();
    }

    // ---- epilogue: bias + store (fp32 or fp16) + per-group partial stats ---
    const int gid  = lane >> 2;
    const int tid4 = lane & 3;
    const int Cg   = M >> 3;
    const int ngt  = 128 / Cg;
    float ps[4] = {0.f, 0.f, 0.f, 0.f};
    float pq[4] = {0.f, 0.f, 0.f, 0.f};
#pragma unroll
    for (int mf = 0; mf < 4; mf++) {
        const int lg = (wm + mf * 16) / Cg;
        const int m = m0 + wm + mf * 16 + gid;
        const float bm0 = bias[m];
        const float bm8 = bias[m + 8];
#pragma unroll
        for (int nf = 0; nf < 4; nf++) {
            const int n = n0 + wn + nf * 8 + 2 * tid4;
            float a0 = acc[mf][nf][0] + bm0, a1 = acc[mf][nf][1] + bm0;
            float a2 = acc[mf][nf][2] + bm8, a3 = acc[mf][nf][3] + bm8;
            if (Yf) {
                float* y0 = Yf + ((size_t)b * M + m) * NPT + n;
                float* y8 = Yf + ((size_t)b * M + m + 8) * NPT + n;
                *reinterpret_cast<float2*>(y0) = make_float2(a0, a1);
                *reinterpret_cast<float2*>(y8) = make_float2(a2, a3);
            } else {
                __half* y0 = Yh + ((size_t)b * M + m) * NPT + n;
                __half* y8 = Yh + ((size_t)b * M + m + 8) * NPT + n;
                *reinterpret_cast<__half2*>(y0) = __floats2half2_rn(a0, a1);
                *reinterpret_cast<__half2*>(y8) = __floats2half2_rn(a2, a3);
            }
            ps[lg] += a0 + a1 + a2 + a3;
            pq[lg] += a0 * a0 + a1 * a1 + a2 * a2 + a3 * a3;
        }
    }
#pragma unroll
    for (int g = 0; g < 4; g++)
#pragma unroll
        for (int o = 16; o > 0; o >>= 1) {
            ps[g] += __shfl_xor_sync(0xFFFFFFFF, ps[g], o);
            pq[g] += __shfl_xor_sync(0xFFFFFFFF, pq[g], o);
        }
    float* red = reinterpret_cast<float*>(smem);
    __syncthreads();
    if (lane == 0) {
#pragma unroll
        for (int g = 0; g < 4; g++) {
            red[(g * 8 + wid) * 2 + 0] = ps[g];
            red[(g * 8 + wid) * 2 + 1] = pq[g];
        }
    }
    __syncthreads();
    if (tid < (unsigned)ngt) {
        float s = 0.f, q = 0.f;
        for (int w = 0; w < 8; w++) {
            s += red[(tid * 8 + w) * 2 + 0];
            q += red[(tid * 8 + w) * 2 + 1];
        }
        int bg = b * NGRP + m0 / Cg + tid;
        g_psum[bg * NTILE + blockIdx.x] = s;
        g_psq [bg * NTILE + blockIdx.x] = q;
    }
}

// ---------------- FiLM scale/shift ------------------------------------------
__global__ void scaleshift_kernel(const float* __restrict__ t_emb,
                                  const float* __restrict__ c_emb,
                                  const float* __restrict__ tw,
                                  const float* __restrict__ tb,
                                  const float* __restrict__ cw,
                                  const float* __restrict__ cb) {
    __shared__ float te[C_OUT], ce[C_OUT];
    const int b = blockIdx.x;
    const int c = threadIdx.x;
    te[c] = t_emb[b * C_OUT + c];
    ce[c] = c_emb[b * C_OUT + c];
    __syncthreads();
    float sc = tb[c] + cb[c];
    float sh = tb[c + C_OUT] + cb[c + C_OUT];
    const float* twr_s = tw + (size_t)c * C_OUT;
    const float* twr_h = tw + (size_t)(c + C_OUT) * C_OUT;
    const float* cwr_s = cw + (size_t)c * C_OUT;
    const float* cwr_h = cw + (size_t)(c + C_OUT) * C_OUT;
    for (int k = 0; k < C_OUT; k++) {
        sc += te[k] * twr_s[k] + ce[k] * cwr_s[k];
        sh += te[k] * twr_h[k] + ce[k] * cwr_h[k];
    }
    g_scale[b * C_OUT + c] = sc;
    g_shift[b * C_OUT + c] = sh;
}

// -------- final: out = GN(h2)*(1+scale)+shift + x_norm (same layout) --------
__global__ void final_kernel(const float* __restrict__ g2w,
                             const float* __restrict__ g2b,
                             float* __restrict__ out) {
    const size_t i4 = ((size_t)blockIdx.x * 256 + threadIdx.x) * 4;
    const int c  = (int)((i4 / NPT) % C_OUT);
    const int bc = (int)(i4 / NPT);
    const int bg = (int)(i4 / ((size_t)(C_OUT / NGRP) * NPT));
    const float m = g_stats[bg * 2 + 0];
    const float r = g_stats[bg * 2 + 1];
    const float gsc = r * g2w[c];
    const float gsh = g2b[c] - m * gsc;
    const float fs = 1.f + g_scale[bc];
    const float fh = g_shift[bc];
    float4 h = *reinterpret_cast<const float4*>(g_h2 + i4);
    uint2 xu = *reinterpret_cast<const uint2*>(g_xh + i4);
    __half2* xh = reinterpret_cast<__half2*>(&xu);
    float2 x01 = __half22float2(xh[0]);
    float2 x23 = __half22float2(xh[1]);
    float4 o;
    o.x = (h.x * gsc + gsh) * fs + fh + x01.x;
    o.y = (h.y * gsc + gsh) * fs + fh + x01.y;
    o.z = (h.z * gsc + gsh) * fs + fh + x23.x;
    o.w = (h.w * gsc + gsh) * fs + fh + x23.y;
    *reinterpret_cast<float4*>(out + i4) = o;
}

// ======================= launch =============================================
extern "C" void kernel_launch(void* const* d_in, const int* in_sizes, int n_in,
                              void* d_out, int out_size) {
    const float* xyz1    = (const float*)d_in[0];
    const float* points1 = (const float*)d_in[1];
    const float* xyz2    = (const float*)d_in[2];
    const float* points2 = (const float*)d_in[3];
    const float* t_emb   = (const float*)d_in[4];
    const float* c_emb   = (const float*)d_in[5];
    const float* mlp_w   = (const float*)d_in[6];
    const float* mlp_b   = (const float*)d_in[7];
    const float* mlp_gw  = (const float*)d_in[8];
    const float* mlp_gb  = (const float*)d_in[9];
    const float* c1w     = (const float*)d_in[10];
    const float* c1b     = (const float*)d_in[11];
    const float* g1w     = (const float*)d_in[12];
    const float* g1b     = (const float*)d_in[13];
    const float* c2w     = (const float*)d_in[14];
    const float* c2b     = (const float*)d_in[15];
    const float* g2w     = (const float*)d_in[16];
    const float* g2b     = (const float*)d_in[17];
    const float* tw      = (const float*)d_in[18];
    const float* tb      = (const float*)d_in[19];
    const float* cw      = (const float*)d_in[20];
    const float* cb      = (const float*)d_in[21];
    float* out = (float*)d_out;

    cudaFuncSetAttribute(gemm_mma_kernel,
                         cudaFuncAttributeMaxDynamicSharedMemorySize,
                         GEMM_SMEM_BYTES);

    float *p_h2, *p_stats;
    cudaGetSymbolAddress((void**)&p_h2, g_h2);
    cudaGetSymbolAddress((void**)&p_stats, g_stats);
    __half *p_nph, *p_xh, *p_h1h, *pWnp, *pW1, *pW2;
    cudaGetSymbolAddress((void**)&p_nph, g_nph);
    cudaGetSymbolAddress((void**)&p_xh, g_xh);
    cudaGetSymbolAddress((void**)&p_h1h, g_h1h);
    cudaGetSymbolAddress((void**)&pWnp, g_Wnp);
    cudaGetSymbolAddress((void**)&pW1, g_W1);
    cudaGetSymbolAddress((void**)&pW2, g_W2);

    // 1) independent prep
    knn3_kernel<<<dim3(NPT / 256, NB), 256>>>(xyz1, xyz2);
    build_np_kernel<<<NB * C_NP, 256>>>(points1, points2);
    scaleshift_kernel<<<NB, 256>>>(t_emb, c_emb, tw, tb, cw, cb);
    wconv_kernel<<<(C_OUT * C_NP / 2 + 255) / 256, 256>>>(mlp_w, pWnp, C_OUT * C_NP);
    wconv_kernel<<<(C_E * C_OUT / 2 + 255) / 256, 256>>>(c1w, pW1, C_E * C_OUT);
    wconv_kernel<<<(C_OUT * C_E / 2 + 255) / 256, 256>>>(c2w, pW2, C_OUT * C_E);

    // 2) GEMM1 (+stats): x_raw(fp16) = mlp_w @ np + mlp_b
    gemm_mma_kernel<<<dim3(NTILE, C_OUT / 128, NB), 256, GEMM_SMEM_BYTES>>>(
        pWnp, p_nph, mlp_b, nullptr, p_xh, C_OUT, C_NP);
    gn_fin_kernel<<<1, 128>>>(C_OUT);

    // 3) x := silu(gn(x_raw)) in place
    norm_kernel<<<(int)(((size_t)NB * C_OUT * NPT) / 2048), 256>>>(
        p_xh, mlp_gw, mlp_gb, p_stats, C_OUT);

    // 4) GEMM2 (+stats): h1_raw(fp16) = c1w @ x + c1b
    gemm_mma_kernel<<<dim3(NTILE, C_E / 128, NB), 256, GEMM_SMEM_BYTES>>>(
        pW1, p_xh, c1b, nullptr, p_h1h, C_E, C_OUT);
    gn_fin_kernel<<<1, 128>>>(C_E);

    // 5) h1 := silu(gn(h1_raw)) in place
    norm_kernel<<<(int)(((size_t)NB * C_E * NPT) / 2048), 256>>>(
        p_h1h, g1w, g1b, p_stats, C_E);

    // 6) GEMM3 (+stats): h2_raw(fp32) = c2w @ h1 + c2b
    gemm_mma_kernel<<<dim3(NTILE, C_OUT / 128, NB), 256, GEMM_SMEM_BYTES>>>(
        pW2, p_h1h, c2b, p_h2, nullptr, C_OUT, C_E);
    gn_fin_kernel<<<1, 128>>>(C_OUT);

    // 7) out = gn(h2)*(1+scale) + shift + x_norm
    final_kernel<<<(int)(((size_t)NB * C_OUT * NPT) / 1024), 256>>>(g2w, g2b, out);
}

// round 13
// speedup vs baseline: 4.4362x; 1.0209x over previous
#include <cuda_runtime.h>
#include <cuda_fp16.h>
#include <cstdint>
#include <math.h>

#define NB     8
#define NPT    8192
#define SPT    2048
#define C_IN   256
#define C_SKIP 128
#define C_NP   384
#define C_OUT  256
#define C_E    1024
#define NGRP   8
#define NTILE  (NPT / 128)   // 64 n-tiles per GEMM

// ---------------- scratch (device globals; no allocation allowed) -----------
static __device__ __half g_nph[(size_t)NB * C_NP * NPT];   // new_points fp16 [C,N]
static __device__ __half g_xh [(size_t)NB * C_OUT * NPT];  // x raw -> normalized in place
static __device__ __half g_h1h[(size_t)NB * C_E * NPT];    // h1 raw -> normalized in place
static __device__ __half g_h2h[(size_t)NB * C_OUT * NPT];  // h2 raw fp16
static __device__ float g_w3[(size_t)NB * NPT * 3];
static __device__ int   g_i3[(size_t)NB * NPT * 3];
static __device__ float g_psum[NB * NGRP * NTILE];
static __device__ float g_psq [NB * NGRP * NTILE];
static __device__ float g_stats[NB * NGRP * 2];
static __device__ float g_scale[NB * C_OUT];
static __device__ float g_shift[NB * C_OUT];

// fp16 weights [M,K] K-contiguous
static __device__ __half g_Wnp[C_OUT * C_NP];
static __device__ __half g_W1 [C_E * C_OUT];
static __device__ __half g_W2 [C_OUT * C_E];

__device__ __forceinline__ uint32_t smem_u32(const void* p) {
    uint32_t a;
    asm("{ .reg .u64 t; cvta.to.shared.u64 t, %1; cvt.u32.u64 %0, t; }"
        : "=r"(a) : "l"(p));
    return a;
}

// ======================= 3-NN + weights =====================================
__global__ void knn3_kernel(const float* __restrict__ xyz1,
                            const float* __restrict__ xyz2) {
    __shared__ float sx[SPT], sy[SPT], sz[SPT], sq[SPT];
    const int b = blockIdx.y;
    const float* x2 = xyz2 + (size_t)b * 3 * SPT;
    for (int s = threadIdx.x; s < SPT; s += blockDim.x) {
        float qx = x2[s], qy = x2[SPT + s], qz = x2[2 * SPT + s];
        sx[s] = qx; sy[s] = qy; sz[s] = qz;
        sq[s] = qx * qx + qy * qy + qz * qz;
    }
    __syncthreads();
    const int n = blockIdx.x * blockDim.x + threadIdx.x;
    const float* x1 = xyz1 + (size_t)b * 3 * NPT;
    const float px = x1[n], py = x1[NPT + n], pz = x1[2 * NPT + n];
    const float pn = px * px + py * py + pz * pz;
    float d0 = 3.4e38f, d1 = 3.4e38f, d2 = 3.4e38f;
    int   i0 = 0, i1 = 0, i2 = 0;
    for (int s = 0; s < SPT; s++) {
        float d = -2.f * (px * sx[s] + py * sy[s] + pz * sz[s]) + pn + sq[s];
        if (d < d0)      { d2 = d1; i2 = i1; d1 = d0; i1 = i0; d0 = d; i0 = s; }
        else if (d < d1) { d2 = d1; i2 = i1; d1 = d;  i1 = s; }
        else if (d < d2) { d2 = d;  i2 = s; }
    }
    float r0 = 1.f / (d0 + 1e-8f);
    float r1 = 1.f / (d1 + 1e-8f);
    float r2 = 1.f / (d2 + 1e-8f);
    float inv = 1.f / (r0 + r1 + r2);
    size_t o = ((size_t)b * NPT + n) * 3;
    g_w3[o + 0] = r0 * inv; g_w3[o + 1] = r1 * inv; g_w3[o + 2] = r2 * inv;
    g_i3[o + 0] = i0;       g_i3[o + 1] = i1;       g_i3[o + 2] = i2;
}

// ---------------- build new_points fp16 [C,N] --------------------------------
__global__ void build_np_kernel(const float* __restrict__ points1,
                                const float* __restrict__ points2) {
    const int bc = blockIdx.x;
    const int b = bc / C_NP;
    const int c = bc % C_NP;
    __half* dst = g_nph + ((size_t)b * C_NP + c) * NPT;
    if (c < C_SKIP) {
        const float* src = points1 + ((size_t)b * C_SKIP + c) * NPT;
        for (int n = threadIdx.x * 2; n < NPT; n += blockDim.x * 2) {
            float2 v = *reinterpret_cast<const float2*>(src + n);
            *reinterpret_cast<__half2*>(dst + n) = __floats2half2_rn(v.x, v.y);
        }
    } else {
        __shared__ float row[SPT];
        const float* src = points2 + ((size_t)b * C_IN + (c - C_SKIP)) * SPT;
        for (int s = threadIdx.x; s < SPT; s += blockDim.x) row[s] = src[s];
        __syncthreads();
        for (int n = threadIdx.x * 2; n < NPT; n += blockDim.x * 2) {
            size_t o = ((size_t)b * NPT + n) * 3;
            float v0 = g_w3[o + 0] * row[g_i3[o + 0]]
                     + g_w3[o + 1] * row[g_i3[o + 1]]
                     + g_w3[o + 2] * row[g_i3[o + 2]];
            float v1 = g_w3[o + 3] * row[g_i3[o + 3]]
                     + g_w3[o + 4] * row[g_i3[o + 4]]
                     + g_w3[o + 5] * row[g_i3[o + 5]];
            *reinterpret_cast<__half2*>(dst + n) = __floats2half2_rn(v0, v1);
        }
    }
}

// ---------------- weight convert fp32 -> fp16 -------------------------------
__global__ void wconv_kernel(const float* __restrict__ w,
                             __half* __restrict__ o, int n) {
    int i = (blockIdx.x * 256 + threadIdx.x) * 2;
    if (i < n) {
        float2 v = *reinterpret_cast<const float2*>(w + i);
        *reinterpret_cast<__half2*>(o + i) = __floats2half2_rn(v.x, v.y);
    }
}

// ---------------- in-place GN + SiLU (elementwise, [C,N] layout) ------------
__global__ void norm_kernel(__half* __restrict__ x,
                            const float* __restrict__ gw,
                            const float* __restrict__ gb,
                            const float* __restrict__ stats, int C) {
    const size_t i8 = ((size_t)blockIdx.x * 256 + threadIdx.x) * 8;
    const int c  = (int)((i8 / NPT) % C);
    const int bg = (int)(i8 / ((size_t)(C / NGRP) * NPT));
    const float m = stats[bg * 2 + 0];
    const float r = stats[bg * 2 + 1];
    const float sc = r * gw[c];
    const float sh = gb[c] - m * sc;
    uint4 v = *reinterpret_cast<const uint4*>(x + i8);
    __half2* h = reinterpret_cast<__half2*>(&v);
#pragma unroll
    for (int j = 0; j < 4; j++) {
        float2 f = __half22float2(h[j]);
        float a = f.x * sc + sh;
        float b2 = f.y * sc + sh;
        a = a * (1.f / (1.f + expf(-a)));
        b2 = b2 * (1.f / (1.f + expf(-b2)));
        h[j] = __floats2half2_rn(a, b2);
    }
    *reinterpret_cast<uint4*>(x + i8) = v;
}

// ---------------- GN finalize -----------------------------------------------
__global__ void gn_fin_kernel(int C) {
    int bg = threadIdx.x;
    if (bg < NB * NGRP) {
        float sm = 0.f, sq = 0.f;
        for (int t = 0; t < NTILE; t++) {
            sm += g_psum[bg * NTILE + t];
            sq += g_psq [bg * NTILE + t];
        }
        float cnt = (float)((size_t)(C / NGRP) * NPT);
        float m = sm / cnt;
        float var = sq / cnt - m * m;
        g_stats[bg * 2 + 0] = m;
        g_stats[bg * 2 + 1] = rsqrtf(var + 1e-5f);
    }
}

// ======================= mma.sync fp16 GEMM (3-stage pipeline) ==============
// Y[b](M x 8192) = W(MxK) @ X[b](K x 8192) + bias.
// A = W [M,K] k-major; B = X [K,N] n-major via ldmatrix.trans.
// CTA 128x128x32, 256 thr, warp tile 64x32, 1 MMA/frag, 3 cp.async stages.
#define TSTRIDE 40
#define BSTRIDE 136
#define ATILE   (128 * TSTRIDE)
#define BTILE   (32 * BSTRIDE)
#define STAGE_E (ATILE + BTILE)            // 9472 halfs
#define NSTAGE  3
#define GEMM_SMEM_BYTES (NSTAGE * STAGE_E * 2)  // 56832 B

__device__ __forceinline__ void cp16(uint32_t saddr, const void* gaddr) {
    asm volatile("cp.async.cg.shared.global [%0], [%1], 16;"
                 :: "r"(saddr), "l"(gaddr));
}
__device__ __forceinline__ void ldsm_x4(uint32_t* r, uint32_t addr) {
    asm volatile("ldmatrix.sync.aligned.m8n8.x4.shared.b16 {%0,%1,%2,%3}, [%4];"
                 : "=r"(r[0]), "=r"(r[1]), "=r"(r[2]), "=r"(r[3]) : "r"(addr));
}
__device__ __forceinline__ void ldsm_x4_t(uint32_t* r, uint32_t addr) {
    asm volatile("ldmatrix.sync.aligned.m8n8.x4.trans.shared.b16 {%0,%1,%2,%3}, [%4];"
                 : "=r"(r[0]), "=r"(r[1]), "=r"(r[2]), "=r"(r[3]) : "r"(addr));
}
#define MMA_F16(ac, a, b0, b1)                                                \
    asm volatile("mma.sync.aligned.m16n8k16.row.col.f32.f16.f16.f32 "         \
                 "{%0,%1,%2,%3}, {%4,%5,%6,%7}, {%8,%9}, {%0,%1,%2,%3};"      \
                 : "+f"((ac)[0]), "+f"((ac)[1]), "+f"((ac)[2]), "+f"((ac)[3]) \
                 : "r"((a)[0]), "r"((a)[1]), "r"((a)[2]), "r"((a)[3]),        \
                   "r"(b0), "r"(b1))

__global__ void __launch_bounds__(256, 2)
gemm_mma_kernel(const __half* __restrict__ W,
                const __half* __restrict__ X,
                const float* __restrict__ bias,
                __half* __restrict__ Y,
                int M, int K) {
    extern __shared__ __half smem[];
    const uint32_t sb = smem_u32(smem);
    const int tid  = threadIdx.x;
    const int wid  = tid >> 5;
    const int lane = tid & 31;

    const int n0 = blockIdx.x * 128;
    const int m0 = blockIdx.y * 128;
    const int b  = blockIdx.z;
    const __half* XB = X + (size_t)b * K * NPT;

    const int wm = (wid >> 2) * 64;
    const int wn = (wid & 3) * 32;

    float acc[4][4][4];
#pragma unroll
    for (int i = 0; i < 4; i++)
#pragma unroll
        for (int j = 0; j < 4; j++)
#pragma unroll
            for (int q = 0; q < 4; q++) acc[i][j][q] = 0.f;

    const int niter = K >> 5;

    auto load_stage = [&](int s, int k0) {
        const uint32_t aS = sb + (uint32_t)(s * STAGE_E) * 2;
        const uint32_t bS = sb + (uint32_t)(s * STAGE_E + ATILE) * 2;
#pragma unroll
        for (int r = 0; r < 2; r++) {
            int u = tid + r * 256;
            int row = u >> 2, seg = u & 3;
            cp16(aS + (uint32_t)(row * TSTRIDE + seg * 8) * 2,
                 W + (size_t)(m0 + row) * K + k0 + seg * 8);
        }
#pragma unroll
        for (int r = 0; r < 2; r++) {
            int u = tid + r * 256;
            int row = u >> 4, seg = u & 15;
            cp16(bS + (uint32_t)(row * BSTRIDE + seg * 8) * 2,
                 XB + (size_t)(k0 + row) * NPT + n0 + seg * 8);
        }
        asm volatile("cp.async.commit_group;" ::: "memory");
    };

    const int aRow = wm + (lane & 15);
    const int aKof = (lane >> 4) * 8;
    const int bl  = lane & 7;
    const int bg2 = lane >> 3;
    const int bKrow = (bg2 & 1) * 8 + bl;
    const int bNcol = (bg2 >> 1) * 8;

    load_stage(0, 0);
    load_stage(1, 32);

    for (int it = 0; it < niter; it++) {
        if (it + 2 < niter) {
            load_stage((it + 2) % NSTAGE, (it + 2) << 5);
            asm volatile("cp.async.wait_group 2;" ::: "memory");
        } else if (it + 1 < niter) {
            asm volatile("cp.async.wait_group 1;" ::: "memory");
        } else {
            asm volatile("cp.async.wait_group 0;" ::: "memory");
        }
        __syncthreads();

        const int s = it % NSTAGE;
        const uint32_t aS = sb + (uint32_t)(s * STAGE_E) * 2;
        const uint32_t bS = sb + (uint32_t)(s * STAGE_E + ATILE) * 2;

#pragma unroll
        for (int kk = 0; kk < 2; kk++) {
            uint32_t af[4][4], bf[4][2];
#pragma unroll
            for (int mf = 0; mf < 4; mf++) {
                uint32_t off = (uint32_t)((aRow + mf * 16) * TSTRIDE
                                          + kk * 16 + aKof) * 2;
                ldsm_x4(af[mf], aS + off);
            }
#pragma unroll
            for (int p = 0; p < 2; p++) {
                uint32_t off = (uint32_t)((kk * 16 + bKrow) * BSTRIDE
                                          + wn + p * 16 + bNcol) * 2;
                uint32_t r[4];
                ldsm_x4_t(r, bS + off);
                bf[2 * p][0] = r[0]; bf[2 * p][1] = r[1];
                bf[2 * p + 1][0] = r[2]; bf[2 * p + 1][1] = r[3];
            }
#pragma unroll
            for (int mf = 0; mf < 4; mf++)
#pragma unroll
                for (int nf = 0; nf < 4; nf++)
                    MMA_F16(acc[mf][nf], af[mf], bf[nf][0], bf[nf][1]);
        }
        __syncthreads();
    }

    // ---- epilogue: bias + fp16 store + per-group partial stats ----
    const int gid  = lane >> 2;
    const int tid4 = lane & 3;
    const int Cg   = M >> 3;
    const int ngt  = 128 / Cg;
    float ps[4] = {0.f, 0.f, 0.f, 0.f};
    float pq[4] = {0.f, 0.f, 0.f, 0.f};
#pragma unroll
    for (int mf = 0; mf < 4; mf++) {
        const int lg = (wm + mf * 16) / Cg;
        const int m = m0 + wm + mf * 16 + gid;
        const float bm0 = bias[m];
        const float bm8 = bias[m + 8];
#pragma unroll
        for (int nf = 0; nf < 4; nf++) {
            const int n = n0 + wn + nf * 8 + 2 * tid4;
            float a0 = acc[mf][nf][0] + bm0, a1 = acc[mf][nf][1] + bm0;
            float a2 = acc[mf][nf][2] + bm8, a3 = acc[mf][nf][3] + bm8;
            __half* y0 = Y + ((size_t)b * M + m) * NPT + n;
            __half* y8 = Y + ((size_t)b * M + m + 8) * NPT + n;
            *reinterpret_cast<__half2*>(y0) = __floats2half2_rn(a0, a1);
            *reinterpret_cast<__half2*>(y8) = __floats2half2_rn(a2, a3);
            ps[lg] += a0 + a1 + a2 + a3;
            pq[lg] += a0 * a0 + a1 * a1 + a2 * a2 + a3 * a3;
        }
    }
#pragma unroll
    for (int g = 0; g < 4; g++)
#pragma unroll
        for (int o = 16; o > 0; o >>= 1) {
            ps[g] += __shfl_xor_sync(0xFFFFFFFF, ps[g], o);
            pq[g] += __shfl_xor_sync(0xFFFFFFFF, pq[g], o);
        }
    float* red = reinterpret_cast<float*>(smem);
    __syncthreads();
    if (lane == 0) {
#pragma unroll
        for (int g = 0; g < 4; g++) {
            red[(g * 8 + wid) * 2 + 0] = ps[g];
            red[(g * 8 + wid) * 2 + 1] = pq[g];
        }
    }
    __syncthreads();
    if (tid < (unsigned)ngt) {
        float s = 0.f, q = 0.f;
        for (int w = 0; w < 8; w++) {
            s += red[(tid * 8 + w) * 2 + 0];
            q += red[(tid * 8 + w) * 2 + 1];
        }
        int bg = b * NGRP + m0 / Cg + tid;
        g_psum[bg * NTILE + blockIdx.x] = s;
        g_psq [bg * NTILE + blockIdx.x] = q;
    }
}

// ---------------- FiLM scale/shift ------------------------------------------
__global__ void scaleshift_kernel(const float* __restrict__ t_emb,
                                  const float* __restrict__ c_emb,
                                  const float* __restrict__ tw,
                                  const float* __restrict__ tb,
                                  const float* __restrict__ cw,
                                  const float* __restrict__ cb) {
    __shared__ float te[C_OUT], ce[C_OUT];
    const int b = blockIdx.x;
    const int c = threadIdx.x;
    te[c] = t_emb[b * C_OUT + c];
    ce[c] = c_emb[b * C_OUT + c];
    __syncthreads();
    float sc = tb[c] + cb[c];
    float sh = tb[c + C_OUT] + cb[c + C_OUT];
    const float* twr_s = tw + (size_t)c * C_OUT;
    const float* twr_h = tw + (size_t)(c + C_OUT) * C_OUT;
    const float* cwr_s = cw + (size_t)c * C_OUT;
    const float* cwr_h = cw + (size_t)(c + C_OUT) * C_OUT;
    for (int k = 0; k < C_OUT; k++) {
        sc += te[k] * twr_s[k] + ce[k] * cwr_s[k];
        sh += te[k] * twr_h[k] + ce[k] * cwr_h[k];
    }
    g_scale[b * C_OUT + c] = sc;
    g_shift[b * C_OUT + c] = sh;
}

// -------- final: out = GN(h2)*(1+scale)+shift + x_norm ----------------------
__global__ void final_kernel(const float* __restrict__ g2w,
                             const float* __restrict__ g2b,
                             float* __restrict__ out) {
    const size_t i4 = ((size_t)blockIdx.x * 256 + threadIdx.x) * 4;
    const int c  = (int)((i4 / NPT) % C_OUT);
    const int bc = (int)(i4 / NPT);
    const int bg = (int)(i4 / ((size_t)(C_OUT / NGRP) * NPT));
    const float m = g_stats[bg * 2 + 0];
    const float r = g_stats[bg * 2 + 1];
    const float gsc = r * g2w[c];
    const float gsh = g2b[c] - m * gsc;
    const float fs = 1.f + g_scale[bc];
    const float fh = g_shift[bc];
    uint2 hu = *reinterpret_cast<const uint2*>(g_h2h + i4);
    uint2 xu = *reinterpret_cast<const uint2*>(g_xh + i4);
    const __half2* hh = reinterpret_cast<const __half2*>(&hu);
    const __half2* xh = reinterpret_cast<const __half2*>(&xu);
    float2 h01 = __half22float2(hh[0]);
    float2 h23 = __half22float2(hh[1]);
    float2 x01 = __half22float2(xh[0]);
    float2 x23 = __half22float2(xh[1]);
    float4 o;
    o.x = (h01.x * gsc + gsh) * fs + fh + x01.x;
    o.y = (h01.y * gsc + gsh) * fs + fh + x01.y;
    o.z = (h23.x * gsc + gsh) * fs + fh + x23.x;
    o.w = (h23.y * gsc + gsh) * fs + fh + x23.y;
    *reinterpret_cast<float4*>(out + i4) = o;
}

// ======================= launch =============================================
extern "C" void kernel_launch(void* const* d_in, const int* in_sizes, int n_in,
                              void* d_out, int out_size) {
    const float* xyz1    = (const float*)d_in[0];
    const float* points1 = (const float*)d_in[1];
    const float* xyz2    = (const float*)d_in[2];
    const float* points2 = (const float*)d_in[3];
    const float* t_emb   = (const float*)d_in[4];
    const float* c_emb   = (const float*)d_in[5];
    const float* mlp_w   = (const float*)d_in[6];
    const float* mlp_b   = (const float*)d_in[7];
    const float* mlp_gw  = (const float*)d_in[8];
    const float* mlp_gb  = (const float*)d_in[9];
    const float* c1w     = (const float*)d_in[10];
    const float* c1b     = (const float*)d_in[11];
    const float* g1w     = (const float*)d_in[12];
    const float* g1b     = (const float*)d_in[13];
    const float* c2w     = (const float*)d_in[14];
    const float* c2b     = (const float*)d_in[15];
    const float* g2w     = (const float*)d_in[16];
    const float* g2b     = (const float*)d_in[17];
    const float* tw      = (const float*)d_in[18];
    const float* tb      = (const float*)d_in[19];
    const float* cw      = (const float*)d_in[20];
    const float* cb      = (const float*)d_in[21];
    float* out = (float*)d_out;

    cudaFuncSetAttribute(gemm_mma_kernel,
                         cudaFuncAttributeMaxDynamicSharedMemorySize,
                         GEMM_SMEM_BYTES);

    float *p_stats;
    cudaGetSymbolAddress((void**)&p_stats, g_stats);
    __half *p_nph, *p_xh, *p_h1h, *p_h2h, *pWnp, *pW1, *pW2;
    cudaGetSymbolAddress((void**)&p_nph, g_nph);
    cudaGetSymbolAddress((void**)&p_xh, g_xh);
    cudaGetSymbolAddress((void**)&p_h1h, g_h1h);
    cudaGetSymbolAddress((void**)&p_h2h, g_h2h);
    cudaGetSymbolAddress((void**)&pWnp, g_Wnp);
    cudaGetSymbolAddress((void**)&pW1, g_W1);
    cudaGetSymbolAddress((void**)&pW2, g_W2);

    // launch indices 0..4 are prep; index 5 = GEMM1 (ncu -s 5 -c 1 target)
    knn3_kernel<<<dim3(NPT / 256, NB), 256>>>(xyz1, xyz2);                       // 0
    build_np_kernel<<<NB * C_NP, 256>>>(points1, points2);                       // 1
    wconv_kernel<<<(C_OUT * C_NP / 2 + 255) / 256, 256>>>(mlp_w, pWnp, C_OUT * C_NP);  // 2
    wconv_kernel<<<(C_E * C_OUT / 2 + 255) / 256, 256>>>(c1w, pW1, C_E * C_OUT);       // 3
    wconv_kernel<<<(C_OUT * C_E / 2 + 255) / 256, 256>>>(c2w, pW2, C_OUT * C_E);       // 4

    // GEMM1 (+stats): x_raw(fp16) = mlp_w @ np + mlp_b
    gemm_mma_kernel<<<dim3(NTILE, C_OUT / 128, NB), 256, GEMM_SMEM_BYTES>>>(
        pWnp, p_nph, mlp_b, p_xh, C_OUT, C_NP);                                  // 5
    gn_fin_kernel<<<1, 128>>>(C_OUT);

    // x := silu(gn(x_raw)) in place
    norm_kernel<<<(int)(((size_t)NB * C_OUT * NPT) / 2048), 256>>>(
        p_xh, mlp_gw, mlp_gb, p_stats, C_OUT);

    // GEMM2 (+stats): h1_raw(fp16) = c1w @ x + c1b
    gemm_mma_kernel<<<dim3(NTILE, C_E / 128, NB), 256, GEMM_SMEM_BYTES>>>(
        pW1, p_xh, c1b, p_h1h, C_E, C_OUT);
    gn_fin_kernel<<<1, 128>>>(C_E);

    // h1 := silu(gn(h1_raw)) in place
    norm_kernel<<<(int)(((size_t)NB * C_E * NPT) / 2048), 256>>>(
        p_h1h, g1w, g1b, p_stats, C_E);

    // GEMM3 (+stats): h2_raw(fp16) = c2w @ h1 + c2b
    gemm_mma_kernel<<<dim3(NTILE, C_OUT / 128, NB), 256, GEMM_SMEM_BYTES>>>(
        pW2, p_h1h, c2b, p_h2h, C_OUT, C_E);
    gn_fin_kernel<<<1, 128>>>(C_OUT);

    // FiLM (input-only; moved late so GEMM1 is launch #5)
    scaleshift_kernel<<<NB, 256>>>(t_emb, c_emb, tw, tb, cw, cb);

    // out = gn(h2)*(1+scale) + shift + x_norm
    final_kernel<<<(int)(((size_t)NB * C_OUT * NPT) / 1024), 256>>>(g2w, g2b, out);
}